// round 1
// baseline (speedup 1.0000x reference)
#include <cuda_runtime.h>
#include <cuda_bf16.h>
#include <math.h>

// Problem constants (from reference): N=50000, E=800000, IN=128, H=8, EMB=32, OUT=16, EF=7
#define MAXN 50000
#define MAXE 800000
#define INF_DIM 128
#define NCOLS 256          // Aq(64) | Ak(64) | v(128)

// -------- device scratch (no allocation allowed) --------
__device__ int   g_deg[MAXN];
__device__ int   g_cnt[MAXN];
__device__ int   g_offs[MAXN + 1];
__device__ int   g_eidx[MAXE];
__device__ float g_nodeproj[(size_t)MAXN * NCOLS];  // 51.2 MB
__device__ float g_wcat[INF_DIM * NCOLS];           // combined weights [128,256]
__device__ float g_wefc8[8 * 128];                  // Wefc rows 0..6, bias row 7

// ---------------- prep: build combined weights ----------------
// Wcat col layout: c in [0,64):  WqA  (h = c/8, f = c%8; f==7 => bek slot)
//                  c in [64,128): WkA
//                  c in [128,256): Wv
__global__ void prep_kernel(const float* __restrict__ Wq, const float* __restrict__ Wk,
                            const float* __restrict__ Wv, const float* __restrict__ Wek,
                            const float* __restrict__ bek, const float* __restrict__ Wefc,
                            const float* __restrict__ befc)
{
    int idx = blockIdx.x * blockDim.x + threadIdx.x;
    if (idx < INF_DIM * NCOLS) {
        int i = idx >> 8;        // 0..127
        int c = idx & 255;       // 0..255
        float r;
        if (c < 128) {
            const float* Wx = (c < 64) ? Wq : Wk;
            int cc = c & 63;
            int h = cc >> 3, f = cc & 7;
            const float* ekrow = (f < 7) ? (Wek + f * 256) : bek;
            float acc = 0.f;
            #pragma unroll
            for (int m = 0; m < 32; ++m)
                acc = fmaf(Wx[i * 256 + h * 32 + m], ekrow[h * 32 + m], acc);
            r = acc;
        } else {
            r = Wv[i * 128 + (c - 128)];
        }
        g_wcat[idx] = r;
    }
    if (idx < 8 * 128) {
        int f = idx >> 7, c = idx & 127;
        g_wefc8[idx] = (f < 7) ? Wefc[f * 128 + c] : befc[c];
    }
}

// ---------------- CSR build ----------------
__global__ void zero_kernel(int n)
{
    int i = blockIdx.x * blockDim.x + threadIdx.x;
    if (i < n) { g_deg[i] = 0; g_cnt[i] = 0; }
}

__global__ void deg_kernel(const int* __restrict__ dst, int E)
{
    int e = blockIdx.x * blockDim.x + threadIdx.x;
    if (e < E) atomicAdd(&g_deg[dst[e]], 1);
}

__global__ void scan_kernel(int n)
{
    __shared__ int wsum[32];
    __shared__ int carry;
    int t = threadIdx.x;
    int lane = t & 31, wid = t >> 5;
    if (t == 0) carry = 0;
    __syncthreads();
    for (int base = 0; base < n; base += 1024) {
        int i = base + t;
        int v = (i < n) ? g_deg[i] : 0;
        int x = v;
        #pragma unroll
        for (int d = 1; d < 32; d <<= 1) {
            int y = __shfl_up_sync(0xffffffffu, x, d);
            if (lane >= d) x += y;
        }
        if (lane == 31) wsum[wid] = x;
        __syncthreads();
        if (wid == 0) {
            int y = wsum[lane];
            #pragma unroll
            for (int d = 1; d < 32; d <<= 1) {
                int z = __shfl_up_sync(0xffffffffu, y, d);
                if (lane >= d) y += z;
            }
            wsum[lane] = y;
        }
        __syncthreads();
        int block_excl = (wid > 0) ? wsum[wid - 1] : 0;
        int excl = carry + block_excl + (x - v);
        if (i < n) g_offs[i] = excl;
        int block_total = wsum[31];
        __syncthreads();
        if (t == 0) carry += block_total;
        __syncthreads();
    }
    if (t == 0) g_offs[n] = carry;
}

__global__ void scatter_kernel(const int* __restrict__ dst, int E)
{
    int e = blockIdx.x * blockDim.x + threadIdx.x;
    if (e >= E) return;
    int d = dst[e];
    int p = g_offs[d] + atomicAdd(&g_cnt[d], 1);
    g_eidx[p] = e;
}

// ---------------- fused node projection GEMM ----------------
// C[M,256] = A[M,128] @ g_wcat[128,256], fp32
#define BM 64
#define BN 64
#define BK 8
__global__ void __launch_bounds__(256) sgemm_kernel(const float* __restrict__ A, int M)
{
    const int K = INF_DIM, Nc = NCOLS;
    __shared__ float As[BK][BM];
    __shared__ float Bs[BK][BN];
    int tid = threadIdx.x;
    int brow = blockIdx.y * BM, bcol = blockIdx.x * BN;
    int ty = tid >> 4, tx = tid & 15;   // 16x16 threads, 4x4 microtile
    float acc[4][4];
    #pragma unroll
    for (int m = 0; m < 4; ++m)
        #pragma unroll
        for (int nn = 0; nn < 4; ++nn) acc[m][nn] = 0.f;

    for (int k0 = 0; k0 < K; k0 += BK) {
        #pragma unroll
        for (int i = 0; i < 2; ++i) {
            int r = (tid >> 3) + i * 32;
            int kk = tid & 7;
            int gr = brow + r;
            As[kk][r] = (gr < M) ? A[gr * K + k0 + kk] : 0.f;
        }
        #pragma unroll
        for (int i = 0; i < 2; ++i) {
            int kk = (tid >> 6) + i * 4;
            int c = tid & 63;
            Bs[kk][c] = g_wcat[(k0 + kk) * Nc + bcol + c];
        }
        __syncthreads();
        #pragma unroll
        for (int kk = 0; kk < BK; ++kk) {
            float ar[4], br[4];
            #pragma unroll
            for (int m = 0; m < 4; ++m) ar[m] = As[kk][ty * 4 + m];
            #pragma unroll
            for (int nn = 0; nn < 4; ++nn) br[nn] = Bs[kk][tx * 4 + nn];
            #pragma unroll
            for (int m = 0; m < 4; ++m)
                #pragma unroll
                for (int nn = 0; nn < 4; ++nn)
                    acc[m][nn] = fmaf(ar[m], br[nn], acc[m][nn]);
        }
        __syncthreads();
    }
    #pragma unroll
    for (int m = 0; m < 4; ++m) {
        int gr = brow + ty * 4 + m;
        if (gr < M) {
            float4 o = make_float4(acc[m][0], acc[m][1], acc[m][2], acc[m][3]);
            *(float4*)(&g_nodeproj[(size_t)gr * Nc + bcol + tx * 4]) = o;
        }
    }
}

// ---------------- fused edge attention + aggregation ----------------
// One warp per destination node. Lane l: head h=l>>2, j=l&3, channels ch=4l..4l+3.
__global__ void __launch_bounds__(256) edge_attn_kernel(
    const int* __restrict__ src, const float* __restrict__ bond,
    const float* __restrict__ bias, float* __restrict__ out, int n)
{
    int warp = blockIdx.x * (blockDim.x >> 5) + (threadIdx.x >> 5);
    if (warp >= n) return;
    int l = threadIdx.x & 31;
    int nid = warp;
    int jj = l & 3;
    int f0 = 2 * jj, f1 = 2 * jj + 1;      // f1==7 => bias slot (bond=1)
    int start = g_offs[nid], end = g_offs[nid + 1];

    // Ak pair for this lane (dst node fixed for the warp)
    float2 akp = *(const float2*)(&g_nodeproj[(size_t)nid * NCOLS + 64 + 2 * l]);

    int ch = 4 * l;
    float wef[8][4];
    #pragma unroll
    for (int f = 0; f < 8; ++f) {
        float4 w4 = *(const float4*)(&g_wefc8[f * 128 + ch]);
        wef[f][0] = w4.x; wef[f][1] = w4.y; wef[f][2] = w4.z; wef[f][3] = w4.w;
    }
    float4 b4 = *(const float4*)(&bias[ch]);

    // ---- pass 1: per-head max ----
    float mx = -3.4e38f;
    for (int p = start; p < end; ++p) {
        int e = g_eidx[p];
        int s = __ldg(&src[e]);
        float2 aqp = *(const float2*)(&g_nodeproj[(size_t)s * NCOLS + 2 * l]);
        float b0 = __ldg(&bond[e * 7 + f0]);
        float b1 = (f1 < 7) ? __ldg(&bond[e * 7 + f1]) : 1.0f;
        float part = b0 * (aqp.x + akp.x) + b1 * (aqp.y + akp.y);
        part += __shfl_xor_sync(0xffffffffu, part, 1);
        part += __shfl_xor_sync(0xffffffffu, part, 2);
        mx = fmaxf(mx, part);
    }

    // ---- pass 2: unnormalized accumulation ----
    float denom = 0.f;
    float a0 = 0.f, a1 = 0.f, a2 = 0.f, a3 = 0.f;
    for (int p = start; p < end; ++p) {
        int e = g_eidx[p];
        int s = __ldg(&src[e]);
        float bb0 = __ldg(&bond[e * 7 + 0]);
        float bb1 = __ldg(&bond[e * 7 + 1]);
        float bb2 = __ldg(&bond[e * 7 + 2]);
        float bb3 = __ldg(&bond[e * 7 + 3]);
        float bb4 = __ldg(&bond[e * 7 + 4]);
        float bb5 = __ldg(&bond[e * 7 + 5]);
        float bb6 = __ldg(&bond[e * 7 + 6]);
        const float bb7 = 1.0f;

        float2 aqp = *(const float2*)(&g_nodeproj[(size_t)s * NCOLS + 2 * l]);
        float b0 = __ldg(&bond[e * 7 + f0]);
        float b1 = (f1 < 7) ? __ldg(&bond[e * 7 + f1]) : 1.0f;
        float part = b0 * (aqp.x + akp.x) + b1 * (aqp.y + akp.y);
        part += __shfl_xor_sync(0xffffffffu, part, 1);
        part += __shfl_xor_sync(0xffffffffu, part, 2);
        float w = __expf(part - mx);
        denom += w;

        float4 v4 = *(const float4*)(&g_nodeproj[(size_t)s * NCOLS + 128 + ch]);

        float e0, e1, e2, e3;
        e0 = bb0 * wef[0][0]; e1 = bb0 * wef[0][1]; e2 = bb0 * wef[0][2]; e3 = bb0 * wef[0][3];
        e0 = fmaf(bb1, wef[1][0], e0); e1 = fmaf(bb1, wef[1][1], e1); e2 = fmaf(bb1, wef[1][2], e2); e3 = fmaf(bb1, wef[1][3], e3);
        e0 = fmaf(bb2, wef[2][0], e0); e1 = fmaf(bb2, wef[2][1], e1); e2 = fmaf(bb2, wef[2][2], e2); e3 = fmaf(bb2, wef[2][3], e3);
        e0 = fmaf(bb3, wef[3][0], e0); e1 = fmaf(bb3, wef[3][1], e1); e2 = fmaf(bb3, wef[3][2], e2); e3 = fmaf(bb3, wef[3][3], e3);
        e0 = fmaf(bb4, wef[4][0], e0); e1 = fmaf(bb4, wef[4][1], e1); e2 = fmaf(bb4, wef[4][2], e2); e3 = fmaf(bb4, wef[4][3], e3);
        e0 = fmaf(bb5, wef[5][0], e0); e1 = fmaf(bb5, wef[5][1], e1); e2 = fmaf(bb5, wef[5][2], e2); e3 = fmaf(bb5, wef[5][3], e3);
        e0 = fmaf(bb6, wef[6][0], e0); e1 = fmaf(bb6, wef[6][1], e1); e2 = fmaf(bb6, wef[6][2], e2); e3 = fmaf(bb6, wef[6][3], e3);
        e0 = fmaf(bb7, wef[7][0], e0); e1 = fmaf(bb7, wef[7][1], e1); e2 = fmaf(bb7, wef[7][2], e2); e3 = fmaf(bb7, wef[7][3], e3);

        float wv;
        wv = w * v4.x; a0 = fmaf(wv, e0, a0);
        wv = w * v4.y; a1 = fmaf(wv, e1, a1);
        wv = w * v4.z; a2 = fmaf(wv, e2, a2);
        wv = w * v4.w; a3 = fmaf(wv, e3, a3);
    }

    float4 r;
    if (end > start) {
        float inv = 1.0f / denom;
        r.x = fmaf(a0, inv, b4.x);
        r.y = fmaf(a1, inv, b4.y);
        r.z = fmaf(a2, inv, b4.z);
        r.w = fmaf(a3, inv, b4.w);
    } else {
        r = b4;
    }
    *(float4*)(&out[(size_t)nid * 128 + ch]) = r;
}

// ---------------- host launcher ----------------
extern "C" void kernel_launch(void* const* d_in, const int* in_sizes, int n_in,
                              void* d_out, int out_size)
{
    const float* feat = (const float*)d_in[0];
    const float* bond = (const float*)d_in[1];
    const int*   src  = (const int*)d_in[2];
    const int*   dst  = (const int*)d_in[3];
    const float* Wq   = (const float*)d_in[4];
    const float* Wk   = (const float*)d_in[5];
    const float* Wv   = (const float*)d_in[6];
    const float* Wek  = (const float*)d_in[7];
    const float* bek  = (const float*)d_in[8];
    const float* Wefc = (const float*)d_in[9];
    const float* befc = (const float*)d_in[10];
    const float* bias = (const float*)d_in[11];
    float* out = (float*)d_out;

    int N = in_sizes[0] / INF_DIM;   // 50000
    int E = in_sizes[2];             // 800000 (src element count)

    // CSR build + weight prep (independent; sequential on stream)
    zero_kernel<<<(N + 255) / 256, 256>>>(N);
    prep_kernel<<<(INF_DIM * NCOLS + 255) / 256, 256>>>(Wq, Wk, Wv, Wek, bek, Wefc, befc);
    deg_kernel<<<(E + 255) / 256, 256>>>(dst, E);
    scan_kernel<<<1, 1024>>>(N);
    scatter_kernel<<<(E + 255) / 256, 256>>>(dst, E);

    // fused node projections: [N,128] @ [128,256] -> g_nodeproj
    dim3 ggrid(NCOLS / BN, (N + BM - 1) / BM);
    sgemm_kernel<<<ggrid, 256>>>(feat, N);

    // fused edge attention + softmax + aggregation (warp per dst node)
    int warps_per_block = 256 / 32;
    int nblocks = (N + warps_per_block - 1) / warps_per_block;
    edge_attn_kernel<<<nblocks, 256>>>(src, bond, bias, out, N);
}

// round 2
// speedup vs baseline: 1.6383x; 1.6383x over previous
#include <cuda_runtime.h>
#include <cuda_bf16.h>
#include <math.h>

// N=50000, E=800000, IN=128, H=8, EMB=32, OUT=16, EF=7
#define MAXN 50000
#define MAXE 800000
#define INF_DIM 128
#define NCOLS 256          // wcat cols: Aq(64) | Ak(64) | v(128)
#define PA_STRIDE 192      // projA row: Aq(64) | v(128)

// -------- device scratch (no allocation allowed) --------
__device__ int   g_deg[MAXN];
__device__ int   g_cnt[MAXN];
__device__ int   g_offs[MAXN + 1];
__device__ int   g_bsum[64];
__device__ int   g_bbase[64];
__device__ int   g_eidx[MAXE];
__device__ float g_projA[(size_t)MAXN * PA_STRIDE];  // 38.4 MB  [Aq(64)|v(128)]
__device__ float g_projK[(size_t)MAXN * 64];         // 12.8 MB  Ak
__device__ float g_wcat[INF_DIM * NCOLS];            // combined weights [128,256]
__device__ float g_wefc8[8 * 128];                   // Wefc rows 0..6, bias row 7

// ---------------- prep: combined weights ----------------
// wcat col c: [0,64)=WqA (h=c/8,f=c%8; f==7 -> bek), [64,128)=WkA, [128,256)=Wv
__global__ void prep_kernel(const float* __restrict__ Wq, const float* __restrict__ Wk,
                            const float* __restrict__ Wv, const float* __restrict__ Wek,
                            const float* __restrict__ bek, const float* __restrict__ Wefc,
                            const float* __restrict__ befc)
{
    int idx = blockIdx.x * blockDim.x + threadIdx.x;
    if (idx < INF_DIM * NCOLS) {
        int i = idx >> 8;
        int c = idx & 255;
        float r;
        if (c < 128) {
            const float* Wx = (c < 64) ? Wq : Wk;
            int cc = c & 63;
            int h = cc >> 3, f = cc & 7;
            const float* ekrow = (f < 7) ? (Wek + f * 256) : bek;
            float acc = 0.f;
            #pragma unroll
            for (int m = 0; m < 32; ++m)
                acc = fmaf(Wx[i * 256 + h * 32 + m], ekrow[h * 32 + m], acc);
            r = acc;
        } else {
            r = Wv[i * 128 + (c - 128)];
        }
        g_wcat[idx] = r;
    }
    if (idx < 8 * 128) {
        int f = idx >> 7, c = idx & 127;
        g_wefc8[idx] = (f < 7) ? Wefc[f * 128 + c] : befc[c];
    }
}

// ---------------- CSR build ----------------
__global__ void zero_kernel(int n)
{
    int i = blockIdx.x * blockDim.x + threadIdx.x;
    if (i < n) { g_deg[i] = 0; g_cnt[i] = 0; }
}

__global__ void deg_kernel(const int* __restrict__ dst, int E)
{
    int e = blockIdx.x * blockDim.x + threadIdx.x;
    if (e < E) atomicAdd(&g_deg[dst[e]], 1);
}

// block-local exclusive scan of g_deg -> g_offs, block totals -> g_bsum
__global__ void scan_local_kernel(int n)
{
    __shared__ int wsum[32];
    int t = threadIdx.x, lane = t & 31, wid = t >> 5;
    int i = blockIdx.x * 1024 + t;
    int v = (i < n) ? g_deg[i] : 0;
    int x = v;
    #pragma unroll
    for (int d = 1; d < 32; d <<= 1) {
        int y = __shfl_up_sync(0xffffffffu, x, d);
        if (lane >= d) x += y;
    }
    if (lane == 31) wsum[wid] = x;
    __syncthreads();
    if (wid == 0) {
        int y = wsum[lane];
        #pragma unroll
        for (int d = 1; d < 32; d <<= 1) {
            int z = __shfl_up_sync(0xffffffffu, y, d);
            if (lane >= d) y += z;
        }
        wsum[lane] = y;
    }
    __syncthreads();
    int excl = ((wid > 0) ? wsum[wid - 1] : 0) + (x - v);
    if (i < n) g_offs[i] = excl;
    if (t == 1023) g_bsum[blockIdx.x] = wsum[31];
}

// scan block totals -> g_bbase (exclusive), g_offs[n] = grand total
__global__ void scan_base_kernel(int nb, int n)
{
    __shared__ int wsum[32];
    int t = threadIdx.x, lane = t & 31, wid = t >> 5;
    int v = (t < nb) ? g_bsum[t] : 0;
    int x = v;
    #pragma unroll
    for (int d = 1; d < 32; d <<= 1) {
        int y = __shfl_up_sync(0xffffffffu, x, d);
        if (lane >= d) x += y;
    }
    if (lane == 31) wsum[wid] = x;
    __syncthreads();
    if (wid == 0) {
        int y = wsum[lane];
        #pragma unroll
        for (int d = 1; d < 32; d <<= 1) {
            int z = __shfl_up_sync(0xffffffffu, y, d);
            if (lane >= d) y += z;
        }
        wsum[lane] = y;
    }
    __syncthreads();
    int excl = ((wid > 0) ? wsum[wid - 1] : 0) + (x - v);
    if (t < nb) g_bbase[t] = excl;
    if (t == 0) g_offs[n] = wsum[31];
}

__global__ void scan_add_kernel(int n)
{
    int i = blockIdx.x * blockDim.x + threadIdx.x;
    if (i < n) g_offs[i] += g_bbase[i >> 10];
}

__global__ void scatter_kernel(const int* __restrict__ dst, int E)
{
    int e = blockIdx.x * blockDim.x + threadIdx.x;
    if (e >= E) return;
    int d = dst[e];
    int p = g_offs[d] + atomicAdd(&g_cnt[d], 1);
    g_eidx[p] = e;
}

// ---------------- node projection GEMM ----------------
// C[M,256] = A[M,128] @ g_wcat[128,256]; output split into projA / projK.
#define GBM 128
#define GBN 64
#define GBK 16
__global__ void __launch_bounds__(256) sgemm_kernel(const float* __restrict__ A, int M)
{
    __shared__ float As[GBK][GBM];
    __shared__ float Bs[GBK][GBN];
    int tid = threadIdx.x;
    int brow = blockIdx.y * GBM;
    int bcol = blockIdx.x * GBN;
    int ty = tid >> 4, tx = tid & 15;     // 16x16 threads, 8x4 microtile
    float acc[8][4];
    #pragma unroll
    for (int m = 0; m < 8; ++m)
        #pragma unroll
        for (int j = 0; j < 4; ++j) acc[m][j] = 0.f;

    for (int k0 = 0; k0 < INF_DIM; k0 += GBK) {
        #pragma unroll
        for (int i = 0; i < 2; ++i) {
            int q = tid * 2 + i;          // 0..511
            int r = q >> 2;               // 0..127
            int kq = (q & 3) * 4;         // 0,4,8,12
            int gr = brow + r;
            float4 a4 = (gr < M) ? *(const float4*)(&A[(size_t)gr * INF_DIM + k0 + kq])
                                 : make_float4(0.f, 0.f, 0.f, 0.f);
            As[kq + 0][r] = a4.x; As[kq + 1][r] = a4.y;
            As[kq + 2][r] = a4.z; As[kq + 3][r] = a4.w;
        }
        {
            int kk = tid >> 4;
            int c = (tid & 15) * 4;
            *(float4*)(&Bs[kk][c]) = *(const float4*)(&g_wcat[(k0 + kk) * NCOLS + bcol + c]);
        }
        __syncthreads();
        #pragma unroll
        for (int kk = 0; kk < GBK; ++kk) {
            float ar[8], br[4];
            #pragma unroll
            for (int m = 0; m < 8; ++m) ar[m] = As[kk][ty * 8 + m];
            #pragma unroll
            for (int j = 0; j < 4; ++j) br[j] = Bs[kk][tx * 4 + j];
            #pragma unroll
            for (int m = 0; m < 8; ++m)
                #pragma unroll
                for (int j = 0; j < 4; ++j)
                    acc[m][j] = fmaf(ar[m], br[j], acc[m][j]);
        }
        __syncthreads();
    }

    // route output: bcol 0 -> projA[0..63]; 64 -> projK; 128/192 -> projA[64..191]
    float* dstp; int cstart; int stride;
    if (bcol == 64)      { dstp = g_projK; cstart = 0;         stride = 64; }
    else if (bcol == 0)  { dstp = g_projA; cstart = 0;         stride = PA_STRIDE; }
    else                 { dstp = g_projA; cstart = bcol - 64; stride = PA_STRIDE; }

    #pragma unroll
    for (int m = 0; m < 8; ++m) {
        int gr = brow + ty * 8 + m;
        if (gr < M) {
            float4 o = make_float4(acc[m][0], acc[m][1], acc[m][2], acc[m][3]);
            *(float4*)(&dstp[(size_t)gr * stride + cstart + tx * 4]) = o;
        }
    }
}

// ---------------- fused edge attention + aggregation ----------------
// One warp per dst node. Lane l: head h=l>>2, channels ch=4l..4l+3.
// Single pass: softmax without max-subtraction (logits are O(1); shift-invariant).
__global__ void __launch_bounds__(256) edge_attn_kernel(
    const int* __restrict__ src, const float* __restrict__ bond,
    const float* __restrict__ bias, float* __restrict__ out, int n)
{
    int warp = blockIdx.x * (blockDim.x >> 5) + (threadIdx.x >> 5);
    if (warp >= n) return;
    int l = threadIdx.x & 31;
    int jj = l & 3;
    int start = g_offs[warp], end = g_offs[warp + 1];

    float2 akp = *(const float2*)(&g_projK[(size_t)warp * 64 + 2 * l]);

    int ch = 4 * l;
    float wef[8][4];
    #pragma unroll
    for (int f = 0; f < 8; ++f) {
        float4 w4 = *(const float4*)(&g_wefc8[f * 128 + ch]);
        wef[f][0] = w4.x; wef[f][1] = w4.y; wef[f][2] = w4.z; wef[f][3] = w4.w;
    }
    float4 b4 = *(const float4*)(&bias[ch]);

    float denom = 0.f;
    float a0 = 0.f, a1 = 0.f, a2 = 0.f, a3 = 0.f;

    int e = 0, s = 0;
    if (start < end) { e = g_eidx[start]; s = __ldg(&src[e]); }

    for (int p = start; p < end; ++p) {
        int ce = e, cs = s;
        if (p + 1 < end) { e = g_eidx[p + 1]; s = __ldg(&src[e]); }

        const float* bp = &bond[(size_t)ce * 7];
        float bb0 = __ldg(bp + 0);
        float bb1 = __ldg(bp + 1);
        float bb2 = __ldg(bp + 2);
        float bb3 = __ldg(bp + 3);
        float bb4 = __ldg(bp + 4);
        float bb5 = __ldg(bp + 5);
        float bb6 = __ldg(bp + 6);

        float2 aqp = *(const float2*)(&g_projA[(size_t)cs * PA_STRIDE + 2 * l]);
        float4 v4  = *(const float4*)(&g_projA[(size_t)cs * PA_STRIDE + 64 + ch]);

        // lane jj owns bond pair (2jj, 2jj+1); slot 7 is the bias (bond=1)
        float pb0 = (jj == 0) ? bb0 : (jj == 1) ? bb2 : (jj == 2) ? bb4 : bb6;
        float pb1 = (jj == 0) ? bb1 : (jj == 1) ? bb3 : (jj == 2) ? bb5 : 1.0f;

        float part = pb0 * (aqp.x + akp.x) + pb1 * (aqp.y + akp.y);
        part += __shfl_xor_sync(0xffffffffu, part, 1);
        part += __shfl_xor_sync(0xffffffffu, part, 2);
        float w = __expf(part);
        denom += w;

        float e0, e1, e2, e3;
        e0 = bb0 * wef[0][0]; e1 = bb0 * wef[0][1]; e2 = bb0 * wef[0][2]; e3 = bb0 * wef[0][3];
        e0 = fmaf(bb1, wef[1][0], e0); e1 = fmaf(bb1, wef[1][1], e1); e2 = fmaf(bb1, wef[1][2], e2); e3 = fmaf(bb1, wef[1][3], e3);
        e0 = fmaf(bb2, wef[2][0], e0); e1 = fmaf(bb2, wef[2][1], e1); e2 = fmaf(bb2, wef[2][2], e2); e3 = fmaf(bb2, wef[2][3], e3);
        e0 = fmaf(bb3, wef[3][0], e0); e1 = fmaf(bb3, wef[3][1], e1); e2 = fmaf(bb3, wef[3][2], e2); e3 = fmaf(bb3, wef[3][3], e3);
        e0 = fmaf(bb4, wef[4][0], e0); e1 = fmaf(bb4, wef[4][1], e1); e2 = fmaf(bb4, wef[4][2], e2); e3 = fmaf(bb4, wef[4][3], e3);
        e0 = fmaf(bb5, wef[5][0], e0); e1 = fmaf(bb5, wef[5][1], e1); e2 = fmaf(bb5, wef[5][2], e2); e3 = fmaf(bb5, wef[5][3], e3);
        e0 = fmaf(bb6, wef[6][0], e0); e1 = fmaf(bb6, wef[6][1], e1); e2 = fmaf(bb6, wef[6][2], e2); e3 = fmaf(bb6, wef[6][3], e3);
        e0 += wef[7][0]; e1 += wef[7][1]; e2 += wef[7][2]; e3 += wef[7][3];

        float wv;
        wv = w * v4.x; a0 = fmaf(wv, e0, a0);
        wv = w * v4.y; a1 = fmaf(wv, e1, a1);
        wv = w * v4.z; a2 = fmaf(wv, e2, a2);
        wv = w * v4.w; a3 = fmaf(wv, e3, a3);
    }

    float4 r;
    if (end > start) {
        float inv = 1.0f / denom;
        r.x = fmaf(a0, inv, b4.x);
        r.y = fmaf(a1, inv, b4.y);
        r.z = fmaf(a2, inv, b4.z);
        r.w = fmaf(a3, inv, b4.w);
    } else {
        r = b4;
    }
    *(float4*)(&out[(size_t)warp * 128 + ch]) = r;
}

// ---------------- host launcher ----------------
extern "C" void kernel_launch(void* const* d_in, const int* in_sizes, int n_in,
                              void* d_out, int out_size)
{
    const float* feat = (const float*)d_in[0];
    const float* bond = (const float*)d_in[1];
    const int*   src  = (const int*)d_in[2];
    const int*   dst  = (const int*)d_in[3];
    const float* Wq   = (const float*)d_in[4];
    const float* Wk   = (const float*)d_in[5];
    const float* Wv   = (const float*)d_in[6];
    const float* Wek  = (const float*)d_in[7];
    const float* bek  = (const float*)d_in[8];
    const float* Wefc = (const float*)d_in[9];
    const float* befc = (const float*)d_in[10];
    const float* bias = (const float*)d_in[11];
    float* out = (float*)d_out;

    int N = in_sizes[0] / INF_DIM;   // 50000
    int E = in_sizes[2];             // 800000

    int nb = (N + 1023) / 1024;      // 49 scan blocks

    zero_kernel<<<(N + 255) / 256, 256>>>(N);
    prep_kernel<<<(INF_DIM * NCOLS + 255) / 256, 256>>>(Wq, Wk, Wv, Wek, bek, Wefc, befc);
    deg_kernel<<<(E + 255) / 256, 256>>>(dst, E);
    scan_local_kernel<<<nb, 1024>>>(N);
    scan_base_kernel<<<1, 1024>>>(nb, N);
    scan_add_kernel<<<(N + 255) / 256, 256>>>(N);
    scatter_kernel<<<(E + 255) / 256, 256>>>(dst, E);

    dim3 ggrid(NCOLS / GBN, (N + GBM - 1) / GBM);
    sgemm_kernel<<<ggrid, 256>>>(feat, N);

    int warps_per_block = 256 / 32;
    int nblocks = (N + warps_per_block - 1) / warps_per_block;
    edge_attn_kernel<<<nblocks, 256>>>(src, bond, bias, out, N);
}

// round 3
// speedup vs baseline: 1.7868x; 1.0907x over previous
#include <cuda_runtime.h>
#include <cuda_bf16.h>
#include <math.h>

// N=50000, E=800000, IN=128, H=8, EMB=32, OUT=16, EF=7
#define MAXN 50000
#define MAXE 800000
#define INF_DIM 128
#define NCOLS 256          // wcat cols: Aq(64) | Ak(64) | v(128)
#define PA_STRIDE 192      // projA row: Aq(64) | v(128)

// -------- device scratch (no allocation allowed) --------
__device__ int   g_deg[MAXN];
__device__ int   g_cnt[MAXN];
__device__ int   g_offs[MAXN + 1];
__device__ int   g_bsum[64];
__device__ int   g_bbase[64];
__device__ int   g_esrc[MAXE];                        // CSR-permuted src
__device__ float g_ebond[(size_t)MAXE * 8];           // CSR-permuted bond (7) + 1.0
__device__ float g_projA[(size_t)MAXN * PA_STRIDE];   // 38.4 MB  [Aq(64)|v(128)]
__device__ float g_projK[(size_t)MAXN * 64];          // 12.8 MB  Ak
__device__ float g_wcat[INF_DIM * NCOLS];             // combined weights [128,256]
__device__ float g_wefc8[8 * 128];                    // Wefc rows 0..6, bias row 7

// ---------------- prep: combined weights ----------------
__global__ void prep_kernel(const float* __restrict__ Wq, const float* __restrict__ Wk,
                            const float* __restrict__ Wv, const float* __restrict__ Wek,
                            const float* __restrict__ bek, const float* __restrict__ Wefc,
                            const float* __restrict__ befc)
{
    int idx = blockIdx.x * blockDim.x + threadIdx.x;
    if (idx < INF_DIM * NCOLS) {
        int i = idx >> 8;
        int c = idx & 255;
        float r;
        if (c < 128) {
            const float* Wx = (c < 64) ? Wq : Wk;
            int cc = c & 63;
            int h = cc >> 3, f = cc & 7;
            const float* ekrow = (f < 7) ? (Wek + f * 256) : bek;
            float acc = 0.f;
            #pragma unroll
            for (int m = 0; m < 32; ++m)
                acc = fmaf(Wx[i * 256 + h * 32 + m], ekrow[h * 32 + m], acc);
            r = acc;
        } else {
            r = Wv[i * 128 + (c - 128)];
        }
        g_wcat[idx] = r;
    }
    if (idx < 8 * 128) {
        int f = idx >> 7, c = idx & 127;
        g_wefc8[idx] = (f < 7) ? Wefc[f * 128 + c] : befc[c];
    }
}

// ---------------- CSR build ----------------
__global__ void deg_kernel(const int* __restrict__ dst, int E)
{
    int e = blockIdx.x * blockDim.x + threadIdx.x;
    if (e < E) atomicAdd(&g_deg[dst[e]], 1);
}

__global__ void scan_local_kernel(int n)
{
    __shared__ int wsum[32];
    int t = threadIdx.x, lane = t & 31, wid = t >> 5;
    int i = blockIdx.x * 1024 + t;
    int v = (i < n) ? g_deg[i] : 0;
    int x = v;
    #pragma unroll
    for (int d = 1; d < 32; d <<= 1) {
        int y = __shfl_up_sync(0xffffffffu, x, d);
        if (lane >= d) x += y;
    }
    if (lane == 31) wsum[wid] = x;
    __syncthreads();
    if (wid == 0) {
        int y = wsum[lane];
        #pragma unroll
        for (int d = 1; d < 32; d <<= 1) {
            int z = __shfl_up_sync(0xffffffffu, y, d);
            if (lane >= d) y += z;
        }
        wsum[lane] = y;
    }
    __syncthreads();
    int excl = ((wid > 0) ? wsum[wid - 1] : 0) + (x - v);
    if (i < n) g_offs[i] = excl;
    if (t == 1023) g_bsum[blockIdx.x] = wsum[31];
}

__global__ void scan_base_kernel(int nb, int n)
{
    __shared__ int wsum[32];
    int t = threadIdx.x, lane = t & 31, wid = t >> 5;
    int v = (t < nb) ? g_bsum[t] : 0;
    int x = v;
    #pragma unroll
    for (int d = 1; d < 32; d <<= 1) {
        int y = __shfl_up_sync(0xffffffffu, x, d);
        if (lane >= d) x += y;
    }
    if (lane == 31) wsum[wid] = x;
    __syncthreads();
    if (wid == 0) {
        int y = wsum[lane];
        #pragma unroll
        for (int d = 1; d < 32; d <<= 1) {
            int z = __shfl_up_sync(0xffffffffu, y, d);
            if (lane >= d) y += z;
        }
        wsum[lane] = y;
    }
    __syncthreads();
    int excl = ((wid > 0) ? wsum[wid - 1] : 0) + (x - v);
    if (t < nb) g_bbase[t] = excl;
    if (t == 0) g_offs[n] = wsum[31];
}

__global__ void scan_add_kernel(int n)
{
    int i = blockIdx.x * blockDim.x + threadIdx.x;
    if (i < n) g_offs[i] += g_bbase[i >> 10];
}

// scatter: permute src and bond directly into CSR order
__global__ void scatter_kernel(const int* __restrict__ src, const int* __restrict__ dst,
                               const float* __restrict__ bond, int E)
{
    int e = blockIdx.x * blockDim.x + threadIdx.x;
    if (e >= E) return;
    int d = dst[e];
    int p = g_offs[d] + atomicAdd(&g_cnt[d], 1);
    g_esrc[p] = src[e];
    const float* bp = bond + (size_t)e * 7;
    float b0 = __ldg(bp + 0), b1 = __ldg(bp + 1), b2 = __ldg(bp + 2), b3 = __ldg(bp + 3);
    float b4 = __ldg(bp + 4), b5 = __ldg(bp + 5), b6 = __ldg(bp + 6);
    *(float4*)&g_ebond[(size_t)p * 8]     = make_float4(b0, b1, b2, b3);
    *(float4*)&g_ebond[(size_t)p * 8 + 4] = make_float4(b4, b5, b6, 1.0f);
}

// ---------------- node projection GEMM ----------------
#define GBM 128
#define GBN 64
#define GBK 16
__global__ void __launch_bounds__(256) sgemm_kernel(const float* __restrict__ A, int M)
{
    __shared__ float As[GBK][GBM];
    __shared__ float Bs[GBK][GBN];
    int tid = threadIdx.x;
    int brow = blockIdx.y * GBM;
    int bcol = blockIdx.x * GBN;
    int ty = tid >> 4, tx = tid & 15;     // 16x16 threads, 8x4 microtile
    float acc[8][4];
    #pragma unroll
    for (int m = 0; m < 8; ++m)
        #pragma unroll
        for (int j = 0; j < 4; ++j) acc[m][j] = 0.f;

    for (int k0 = 0; k0 < INF_DIM; k0 += GBK) {
        #pragma unroll
        for (int i = 0; i < 2; ++i) {
            int q = tid * 2 + i;          // 0..511
            int r = q >> 2;               // 0..127
            int kq = (q & 3) * 4;
            int gr = brow + r;
            float4 a4 = (gr < M) ? *(const float4*)(&A[(size_t)gr * INF_DIM + k0 + kq])
                                 : make_float4(0.f, 0.f, 0.f, 0.f);
            As[kq + 0][r] = a4.x; As[kq + 1][r] = a4.y;
            As[kq + 2][r] = a4.z; As[kq + 3][r] = a4.w;
        }
        {
            int kk = tid >> 4;
            int c = (tid & 15) * 4;
            *(float4*)(&Bs[kk][c]) = *(const float4*)(&g_wcat[(k0 + kk) * NCOLS + bcol + c]);
        }
        __syncthreads();
        #pragma unroll
        for (int kk = 0; kk < GBK; ++kk) {
            float ar[8], br[4];
            #pragma unroll
            for (int m = 0; m < 8; ++m) ar[m] = As[kk][ty * 8 + m];
            #pragma unroll
            for (int j = 0; j < 4; ++j) br[j] = Bs[kk][tx * 4 + j];
            #pragma unroll
            for (int m = 0; m < 8; ++m)
                #pragma unroll
                for (int j = 0; j < 4; ++j)
                    acc[m][j] = fmaf(ar[m], br[j], acc[m][j]);
        }
        __syncthreads();
    }

    float* dstp; int cstart; int stride;
    if (bcol == 64)      { dstp = g_projK; cstart = 0;         stride = 64; }
    else if (bcol == 0)  { dstp = g_projA; cstart = 0;         stride = PA_STRIDE; }
    else                 { dstp = g_projA; cstart = bcol - 64; stride = PA_STRIDE; }

    #pragma unroll
    for (int m = 0; m < 8; ++m) {
        int gr = brow + ty * 8 + m;
        if (gr < M) {
            float4 o = make_float4(acc[m][0], acc[m][1], acc[m][2], acc[m][3]);
            *(float4*)(&dstp[(size_t)gr * stride + cstart + tx * 4]) = o;
        }
    }
}

// ---------------- fused edge attention + aggregation ----------------
// One warp per dst node. Lane l: head h=l>>2, channels ch=4l..4l+3.
// Single-pass softmax (no max-subtraction; logits O(1), shift-invariant).
__global__ void __launch_bounds__(256) edge_attn_kernel(
    const float* __restrict__ bias, float* __restrict__ out, int n)
{
    int warp = blockIdx.x * (blockDim.x >> 5) + (threadIdx.x >> 5);
    if (warp >= n) return;
    int l = threadIdx.x & 31;
    int jj = l & 3;
    int start = g_offs[warp], end = g_offs[warp + 1];

    float2 akp = *(const float2*)(&g_projK[(size_t)warp * 64 + 2 * l]);

    int ch = 4 * l;
    float wef[8][4];
    #pragma unroll
    for (int f = 0; f < 8; ++f) {
        float4 w4 = *(const float4*)(&g_wefc8[f * 128 + ch]);
        wef[f][0] = w4.x; wef[f][1] = w4.y; wef[f][2] = w4.z; wef[f][3] = w4.w;
    }
    float4 b4 = *(const float4*)(&bias[ch]);

    float denom = 0.f;
    float a0 = 0.f, a1 = 0.f, a2 = 0.f, a3 = 0.f;

    int s = 0;
    if (start < end) s = __ldg(&g_esrc[start]);

    for (int p = start; p < end; ++p) {
        int cs = s;
        if (p + 1 < end) s = __ldg(&g_esrc[p + 1]);

        float4 bx = *(const float4*)(&g_ebond[(size_t)p * 8]);
        float4 by = *(const float4*)(&g_ebond[(size_t)p * 8 + 4]);

        float2 aqp = *(const float2*)(&g_projA[(size_t)cs * PA_STRIDE + 2 * l]);
        float4 v4  = *(const float4*)(&g_projA[(size_t)cs * PA_STRIDE + 64 + ch]);

        // lane jj owns bond pair (2jj, 2jj+1); slot 7 is bias (value 1.0 in by.w)
        float pb0 = (jj == 0) ? bx.x : (jj == 1) ? bx.z : (jj == 2) ? by.x : by.z;
        float pb1 = (jj == 0) ? bx.y : (jj == 1) ? bx.w : (jj == 2) ? by.y : by.w;

        float part = pb0 * (aqp.x + akp.x) + pb1 * (aqp.y + akp.y);
        part += __shfl_xor_sync(0xffffffffu, part, 1);
        part += __shfl_xor_sync(0xffffffffu, part, 2);
        float w = __expf(part);
        denom += w;

        float e0, e1, e2, e3;
        e0 = bx.x * wef[0][0]; e1 = bx.x * wef[0][1]; e2 = bx.x * wef[0][2]; e3 = bx.x * wef[0][3];
        e0 = fmaf(bx.y, wef[1][0], e0); e1 = fmaf(bx.y, wef[1][1], e1); e2 = fmaf(bx.y, wef[1][2], e2); e3 = fmaf(bx.y, wef[1][3], e3);
        e0 = fmaf(bx.z, wef[2][0], e0); e1 = fmaf(bx.z, wef[2][1], e1); e2 = fmaf(bx.z, wef[2][2], e2); e3 = fmaf(bx.z, wef[2][3], e3);
        e0 = fmaf(bx.w, wef[3][0], e0); e1 = fmaf(bx.w, wef[3][1], e1); e2 = fmaf(bx.w, wef[3][2], e2); e3 = fmaf(bx.w, wef[3][3], e3);
        e0 = fmaf(by.x, wef[4][0], e0); e1 = fmaf(by.x, wef[4][1], e1); e2 = fmaf(by.x, wef[4][2], e2); e3 = fmaf(by.x, wef[4][3], e3);
        e0 = fmaf(by.y, wef[5][0], e0); e1 = fmaf(by.y, wef[5][1], e1); e2 = fmaf(by.y, wef[5][2], e2); e3 = fmaf(by.y, wef[5][3], e3);
        e0 = fmaf(by.z, wef[6][0], e0); e1 = fmaf(by.z, wef[6][1], e1); e2 = fmaf(by.z, wef[6][2], e2); e3 = fmaf(by.z, wef[6][3], e3);
        e0 += wef[7][0]; e1 += wef[7][1]; e2 += wef[7][2]; e3 += wef[7][3];

        float wv;
        wv = w * v4.x; a0 = fmaf(wv, e0, a0);
        wv = w * v4.y; a1 = fmaf(wv, e1, a1);
        wv = w * v4.z; a2 = fmaf(wv, e2, a2);
        wv = w * v4.w; a3 = fmaf(wv, e3, a3);
    }

    float4 r;
    if (end > start) {
        float inv = 1.0f / denom;
        r.x = fmaf(a0, inv, b4.x);
        r.y = fmaf(a1, inv, b4.y);
        r.z = fmaf(a2, inv, b4.z);
        r.w = fmaf(a3, inv, b4.w);
    } else {
        r = b4;
    }
    *(float4*)(&out[(size_t)warp * 128 + ch]) = r;
}

// ---------------- host launcher ----------------
extern "C" void kernel_launch(void* const* d_in, const int* in_sizes, int n_in,
                              void* d_out, int out_size)
{
    const float* feat = (const float*)d_in[0];
    const float* bond = (const float*)d_in[1];
    const int*   src  = (const int*)d_in[2];
    const int*   dst  = (const int*)d_in[3];
    const float* Wq   = (const float*)d_in[4];
    const float* Wk   = (const float*)d_in[5];
    const float* Wv   = (const float*)d_in[6];
    const float* Wek  = (const float*)d_in[7];
    const float* bek  = (const float*)d_in[8];
    const float* Wefc = (const float*)d_in[9];
    const float* befc = (const float*)d_in[10];
    const float* bias = (const float*)d_in[11];
    float* out = (float*)d_out;

    int N = in_sizes[0] / INF_DIM;   // 50000
    int E = in_sizes[2];             // 800000
    int nb = (N + 1023) / 1024;      // 49 scan blocks

    void *deg_ptr = nullptr, *cnt_ptr = nullptr;
    cudaGetSymbolAddress(&deg_ptr, g_deg);
    cudaGetSymbolAddress(&cnt_ptr, g_cnt);

    // fork: prep + sgemm on side stream, CSR chain on main stream
    cudaStream_t s1;
    cudaStreamCreateWithFlags(&s1, cudaStreamNonBlocking);
    cudaEvent_t evFork, evJoin;
    cudaEventCreateWithFlags(&evFork, cudaEventDisableTiming);
    cudaEventCreateWithFlags(&evJoin, cudaEventDisableTiming);

    cudaEventRecord(evFork, 0);
    cudaStreamWaitEvent(s1, evFork, 0);

    // side stream: weight prep + node projection GEMM
    prep_kernel<<<(INF_DIM * NCOLS + 255) / 256, 256, 0, s1>>>(Wq, Wk, Wv, Wek, bek, Wefc, befc);
    dim3 ggrid(NCOLS / GBN, (N + GBM - 1) / GBM);
    sgemm_kernel<<<ggrid, 256, 0, s1>>>(feat, N);
    cudaEventRecord(evJoin, s1);

    // main stream: CSR build + edge permutation
    cudaMemsetAsync(deg_ptr, 0, (size_t)N * sizeof(int), 0);
    cudaMemsetAsync(cnt_ptr, 0, (size_t)N * sizeof(int), 0);
    deg_kernel<<<(E + 255) / 256, 256>>>(dst, E);
    scan_local_kernel<<<nb, 1024>>>(N);
    scan_base_kernel<<<1, 1024>>>(nb, N);
    scan_add_kernel<<<(N + 255) / 256, 256>>>(N);
    scatter_kernel<<<(E + 255) / 256, 256>>>(src, dst, bond, E);

    cudaStreamWaitEvent(0, evJoin, 0);

    // fused edge attention + softmax + aggregation
    int warps_per_block = 256 / 32;
    int nblocks = (N + warps_per_block - 1) / warps_per_block;
    edge_attn_kernel<<<nblocks, 256>>>(bias, out, N);

    cudaEventDestroy(evFork);
    cudaEventDestroy(evJoin);
    cudaStreamDestroy(s1);
}

// round 4
// speedup vs baseline: 1.8114x; 1.0138x over previous
#include <cuda_runtime.h>
#include <cuda_bf16.h>
#include <math.h>

// N=50000, E=800000, IN=128, H=8, EMB=32, OUT=16, EF=7
#define MAXN 50000
#define MAXE 800000
#define INF_DIM 128
#define NCOLS 256          // wcat cols: Aq(64) | Ak(64) | v(128)
#define PA_STRIDE 192      // projA row: Aq(64) | v(128)

// -------- device scratch --------
__device__ int   g_deg[MAXN];
__device__ int   g_cnt[MAXN];
__device__ int   g_offs[MAXN + 1];
__device__ int   g_bsum[64];
__device__ int   g_bbase[64];
__device__ int   g_esrc[MAXE];
__device__ float g_ebond[(size_t)MAXE * 8];
__device__ float g_projA[(size_t)MAXN * PA_STRIDE];
__device__ float g_projK[(size_t)MAXN * 64];
__device__ float g_wcat[INF_DIM * NCOLS];
__device__ float g_wefc8[8 * 128];

// ---------------- prep: combined weights ----------------
__global__ void prep_kernel(const float* __restrict__ Wq, const float* __restrict__ Wk,
                            const float* __restrict__ Wv, const float* __restrict__ Wek,
                            const float* __restrict__ bek, const float* __restrict__ Wefc,
                            const float* __restrict__ befc)
{
    int idx = blockIdx.x * blockDim.x + threadIdx.x;
    if (idx < INF_DIM * NCOLS) {
        int i = idx >> 8;
        int c = idx & 255;
        float r;
        if (c < 128) {
            const float* Wx = (c < 64) ? Wq : Wk;
            int cc = c & 63;
            int h = cc >> 3, f = cc & 7;
            const float* ekrow = (f < 7) ? (Wek + f * 256) : bek;
            float acc = 0.f;
            #pragma unroll
            for (int m = 0; m < 32; ++m)
                acc = fmaf(Wx[i * 256 + h * 32 + m], ekrow[h * 32 + m], acc);
            r = acc;
        } else {
            r = Wv[i * 128 + (c - 128)];
        }
        g_wcat[idx] = r;
    }
    if (idx < 8 * 128) {
        int f = idx >> 7, c = idx & 127;
        g_wefc8[idx] = (f < 7) ? Wefc[f * 128 + c] : befc[c];
    }
}

// ---------------- CSR build ----------------
__global__ void deg_kernel(const int* __restrict__ dst, int E)
{
    int e = blockIdx.x * blockDim.x + threadIdx.x;
    if (e < E) atomicAdd(&g_deg[dst[e]], 1);
}

__global__ void scan_local_kernel(int n)
{
    __shared__ int wsum[32];
    int t = threadIdx.x, lane = t & 31, wid = t >> 5;
    int i = blockIdx.x * 1024 + t;
    int v = (i < n) ? g_deg[i] : 0;
    int x = v;
    #pragma unroll
    for (int d = 1; d < 32; d <<= 1) {
        int y = __shfl_up_sync(0xffffffffu, x, d);
        if (lane >= d) x += y;
    }
    if (lane == 31) wsum[wid] = x;
    __syncthreads();
    if (wid == 0) {
        int y = wsum[lane];
        #pragma unroll
        for (int d = 1; d < 32; d <<= 1) {
            int z = __shfl_up_sync(0xffffffffu, y, d);
            if (lane >= d) y += z;
        }
        wsum[lane] = y;
    }
    __syncthreads();
    int excl = ((wid > 0) ? wsum[wid - 1] : 0) + (x - v);
    if (i < n) g_offs[i] = excl;
    if (t == 1023) g_bsum[blockIdx.x] = wsum[31];
}

// scan block totals -> g_bbase (exclusive); also g_offs[n] = local total of n's block
__global__ void scan_base_kernel(int nb, int n)
{
    __shared__ int wsum[32];
    int t = threadIdx.x, lane = t & 31, wid = t >> 5;
    int v = (t < nb) ? g_bsum[t] : 0;
    int x = v;
    #pragma unroll
    for (int d = 1; d < 32; d <<= 1) {
        int y = __shfl_up_sync(0xffffffffu, x, d);
        if (lane >= d) x += y;
    }
    if (lane == 31) wsum[wid] = x;
    __syncthreads();
    if (wid == 0) {
        int y = wsum[lane];
        #pragma unroll
        for (int d = 1; d < 32; d <<= 1) {
            int z = __shfl_up_sync(0xffffffffu, y, d);
            if (lane >= d) y += z;
        }
        wsum[lane] = y;
    }
    __syncthreads();
    int excl = ((wid > 0) ? wsum[wid - 1] : 0) + (x - v);
    if (t < nb) g_bbase[t] = excl;
    if (t == 0) g_offs[n] = g_bsum[n >> 10];   // so end(last node) = bsum+bbase = E
}

// scatter: offs = g_offs[d] + g_bbase[d>>10] inline (scan_add fused away)
__global__ void scatter_kernel(const int* __restrict__ src, const int* __restrict__ dst,
                               const float* __restrict__ bond, int E)
{
    int e = blockIdx.x * blockDim.x + threadIdx.x;
    if (e >= E) return;
    int d = dst[e];
    int p = g_offs[d] + g_bbase[d >> 10] + atomicAdd(&g_cnt[d], 1);
    g_esrc[p] = src[e];
    const float* bp = bond + (size_t)e * 7;
    float b0 = __ldg(bp + 0), b1 = __ldg(bp + 1), b2 = __ldg(bp + 2), b3 = __ldg(bp + 3);
    float b4 = __ldg(bp + 4), b5 = __ldg(bp + 5), b6 = __ldg(bp + 6);
    *(float4*)&g_ebond[(size_t)p * 8]     = make_float4(b0, b1, b2, b3);
    *(float4*)&g_ebond[(size_t)p * 8 + 4] = make_float4(b4, b5, b6, 1.0f);
}

// ---------------- node projection GEMM (128x128x16, 8x8 microtile) ----------------
#define GBM 128
#define GBN 128
#define GBK 16
__global__ void __launch_bounds__(256) sgemm_kernel(const float* __restrict__ A, int M)
{
    __shared__ float As[GBK][GBM];
    __shared__ float Bs[GBK][GBN];
    int tid = threadIdx.x;
    int brow = blockIdx.y * GBM;
    int bcol = blockIdx.x * GBN;      // 0 or 128
    int ty = tid >> 4, tx = tid & 15; // 16x16 threads, 8x8 microtile
    float acc[8][8];
    #pragma unroll
    for (int m = 0; m < 8; ++m)
        #pragma unroll
        for (int j = 0; j < 8; ++j) acc[m][j] = 0.f;

    for (int k0 = 0; k0 < INF_DIM; k0 += GBK) {
        #pragma unroll
        for (int i = 0; i < 2; ++i) {
            int q = tid * 2 + i;          // 0..511
            int r = q >> 2;               // 0..127
            int kq = (q & 3) * 4;         // 0,4,8,12
            int gr = brow + r;
            float4 a4 = (gr < M) ? *(const float4*)(&A[(size_t)gr * INF_DIM + k0 + kq])
                                 : make_float4(0.f, 0.f, 0.f, 0.f);
            As[kq + 0][r] = a4.x; As[kq + 1][r] = a4.y;
            As[kq + 2][r] = a4.z; As[kq + 3][r] = a4.w;
        }
        #pragma unroll
        for (int i = 0; i < 2; ++i) {
            int q = tid + i * 256;        // 0..511
            int kk = q >> 5;              // 0..15
            int c = (q & 31) * 4;
            *(float4*)(&Bs[kk][c]) = *(const float4*)(&g_wcat[(k0 + kk) * NCOLS + bcol + c]);
        }
        __syncthreads();
        #pragma unroll
        for (int kk = 0; kk < GBK; ++kk) {
            float ar[8], br[8];
            *(float4*)&ar[0] = *(float4*)&As[kk][ty * 8];
            *(float4*)&ar[4] = *(float4*)&As[kk][ty * 8 + 4];
            *(float4*)&br[0] = *(float4*)&Bs[kk][tx * 8];
            *(float4*)&br[4] = *(float4*)&Bs[kk][tx * 8 + 4];
            #pragma unroll
            for (int m = 0; m < 8; ++m)
                #pragma unroll
                for (int j = 0; j < 8; ++j)
                    acc[m][j] = fmaf(ar[m], br[j], acc[m][j]);
        }
        __syncthreads();
    }

    // routing: global col block = bcol + tx*8 (8 cols, never straddles regions)
    int gcol = bcol + tx * 8;
    float* dstp; int cstart; int stride;
    if (gcol < 64)        { dstp = g_projA; cstart = gcol;      stride = PA_STRIDE; }
    else if (gcol < 128)  { dstp = g_projK; cstart = gcol - 64; stride = 64; }
    else                  { dstp = g_projA; cstart = gcol - 64; stride = PA_STRIDE; }

    #pragma unroll
    for (int m = 0; m < 8; ++m) {
        int gr = brow + ty * 8 + m;
        if (gr < M) {
            *(float4*)(&dstp[(size_t)gr * stride + cstart])     = *(float4*)&acc[m][0];
            *(float4*)(&dstp[(size_t)gr * stride + cstart + 4]) = *(float4*)&acc[m][4];
        }
    }
}

// ---------------- fused edge attention + aggregation ----------------
// One warp per dst node; software-pipelined gathers.
__global__ void __launch_bounds__(256) edge_attn_kernel(
    const float* __restrict__ bias, float* __restrict__ out, int n)
{
    int warp = blockIdx.x * (blockDim.x >> 5) + (threadIdx.x >> 5);
    if (warp >= n) return;
    int l = threadIdx.x & 31;
    int jj = l & 3;
    int start = g_offs[warp]     + g_bbase[warp >> 10];
    int end   = g_offs[warp + 1] + g_bbase[(warp + 1) >> 10];

    float2 akp = *(const float2*)(&g_projK[(size_t)warp * 64 + 2 * l]);

    int ch = 4 * l;
    float wef[8][4];
    #pragma unroll
    for (int f = 0; f < 8; ++f) {
        float4 w4 = *(const float4*)(&g_wefc8[f * 128 + ch]);
        wef[f][0] = w4.x; wef[f][1] = w4.y; wef[f][2] = w4.z; wef[f][3] = w4.w;
    }
    float4 b4 = *(const float4*)(&bias[ch]);

    float denom = 0.f;
    float a0 = 0.f, a1 = 0.f, a2 = 0.f, a3 = 0.f;

    int deg = end - start;
    if (deg > 0) {
        int s_cur = __ldg(&g_esrc[start]);
        float2 aqp_c = *(const float2*)(&g_projA[(size_t)s_cur * PA_STRIDE + 2 * l]);
        float4 v4_c  = *(const float4*)(&g_projA[(size_t)s_cur * PA_STRIDE + 64 + ch]);
        int s_nxt = (deg > 1) ? __ldg(&g_esrc[start + 1]) : 0;

        for (int p = 0; p < deg; ++p) {
            float2 aqp_n = make_float2(0.f, 0.f);
            float4 v4_n  = make_float4(0.f, 0.f, 0.f, 0.f);
            if (p + 1 < deg) {
                aqp_n = *(const float2*)(&g_projA[(size_t)s_nxt * PA_STRIDE + 2 * l]);
                v4_n  = *(const float4*)(&g_projA[(size_t)s_nxt * PA_STRIDE + 64 + ch]);
            }
            if (p + 2 < deg) s_nxt = __ldg(&g_esrc[start + p + 2]);

            float4 bx = *(const float4*)(&g_ebond[(size_t)(start + p) * 8]);
            float4 by = *(const float4*)(&g_ebond[(size_t)(start + p) * 8 + 4]);

            float pb0 = (jj == 0) ? bx.x : (jj == 1) ? bx.z : (jj == 2) ? by.x : by.z;
            float pb1 = (jj == 0) ? bx.y : (jj == 1) ? bx.w : (jj == 2) ? by.y : by.w;

            float part = pb0 * (aqp_c.x + akp.x) + pb1 * (aqp_c.y + akp.y);
            part += __shfl_xor_sync(0xffffffffu, part, 1);
            part += __shfl_xor_sync(0xffffffffu, part, 2);
            float w = __expf(part);
            denom += w;

            float e0, e1, e2, e3;
            e0 = bx.x * wef[0][0]; e1 = bx.x * wef[0][1]; e2 = bx.x * wef[0][2]; e3 = bx.x * wef[0][3];
            e0 = fmaf(bx.y, wef[1][0], e0); e1 = fmaf(bx.y, wef[1][1], e1); e2 = fmaf(bx.y, wef[1][2], e2); e3 = fmaf(bx.y, wef[1][3], e3);
            e0 = fmaf(bx.z, wef[2][0], e0); e1 = fmaf(bx.z, wef[2][1], e1); e2 = fmaf(bx.z, wef[2][2], e2); e3 = fmaf(bx.z, wef[2][3], e3);
            e0 = fmaf(bx.w, wef[3][0], e0); e1 = fmaf(bx.w, wef[3][1], e1); e2 = fmaf(bx.w, wef[3][2], e2); e3 = fmaf(bx.w, wef[3][3], e3);
            e0 = fmaf(by.x, wef[4][0], e0); e1 = fmaf(by.x, wef[4][1], e1); e2 = fmaf(by.x, wef[4][2], e2); e3 = fmaf(by.x, wef[4][3], e3);
            e0 = fmaf(by.y, wef[5][0], e0); e1 = fmaf(by.y, wef[5][1], e1); e2 = fmaf(by.y, wef[5][2], e2); e3 = fmaf(by.y, wef[5][3], e3);
            e0 = fmaf(by.z, wef[6][0], e0); e1 = fmaf(by.z, wef[6][1], e1); e2 = fmaf(by.z, wef[6][2], e2); e3 = fmaf(by.z, wef[6][3], e3);
            e0 += wef[7][0]; e1 += wef[7][1]; e2 += wef[7][2]; e3 += wef[7][3];

            float wv;
            wv = w * v4_c.x; a0 = fmaf(wv, e0, a0);
            wv = w * v4_c.y; a1 = fmaf(wv, e1, a1);
            wv = w * v4_c.z; a2 = fmaf(wv, e2, a2);
            wv = w * v4_c.w; a3 = fmaf(wv, e3, a3);

            aqp_c = aqp_n; v4_c = v4_n;
        }
    }

    float4 r;
    if (deg > 0) {
        float inv = 1.0f / denom;
        r.x = fmaf(a0, inv, b4.x);
        r.y = fmaf(a1, inv, b4.y);
        r.z = fmaf(a2, inv, b4.z);
        r.w = fmaf(a3, inv, b4.w);
    } else {
        r = b4;
    }
    *(float4*)(&out[(size_t)warp * 128 + ch]) = r;
}

// ---------------- host launcher ----------------
extern "C" void kernel_launch(void* const* d_in, const int* in_sizes, int n_in,
                              void* d_out, int out_size)
{
    const float* feat = (const float*)d_in[0];
    const float* bond = (const float*)d_in[1];
    const int*   src  = (const int*)d_in[2];
    const int*   dst  = (const int*)d_in[3];
    const float* Wq   = (const float*)d_in[4];
    const float* Wk   = (const float*)d_in[5];
    const float* Wv   = (const float*)d_in[6];
    const float* Wek  = (const float*)d_in[7];
    const float* bek  = (const float*)d_in[8];
    const float* Wefc = (const float*)d_in[9];
    const float* befc = (const float*)d_in[10];
    const float* bias = (const float*)d_in[11];
    float* out = (float*)d_out;

    int N = in_sizes[0] / INF_DIM;   // 50000
    int E = in_sizes[2];             // 800000
    int nb = (N + 1023) / 1024;      // 49

    void *deg_ptr = nullptr, *cnt_ptr = nullptr;
    cudaGetSymbolAddress(&deg_ptr, g_deg);
    cudaGetSymbolAddress(&cnt_ptr, g_cnt);

    cudaStream_t s1;
    cudaStreamCreateWithFlags(&s1, cudaStreamNonBlocking);
    cudaEvent_t evFork, evJoin;
    cudaEventCreateWithFlags(&evFork, cudaEventDisableTiming);
    cudaEventCreateWithFlags(&evJoin, cudaEventDisableTiming);

    cudaEventRecord(evFork, 0);
    cudaStreamWaitEvent(s1, evFork, 0);

    prep_kernel<<<(INF_DIM * NCOLS + 255) / 256, 256, 0, s1>>>(Wq, Wk, Wv, Wek, bek, Wefc, befc);
    dim3 ggrid(NCOLS / GBN, (N + GBM - 1) / GBM);
    sgemm_kernel<<<ggrid, 256, 0, s1>>>(feat, N);
    cudaEventRecord(evJoin, s1);

    cudaMemsetAsync(deg_ptr, 0, (size_t)N * sizeof(int), 0);
    cudaMemsetAsync(cnt_ptr, 0, (size_t)N * sizeof(int), 0);
    deg_kernel<<<(E + 255) / 256, 256>>>(dst, E);
    scan_local_kernel<<<nb, 1024>>>(N);
    scan_base_kernel<<<1, 1024>>>(nb, N);
    scatter_kernel<<<(E + 255) / 256, 256>>>(src, dst, bond, E);

    cudaStreamWaitEvent(0, evJoin, 0);

    int warps_per_block = 256 / 32;
    int nblocks = (N + warps_per_block - 1) / warps_per_block;
    edge_attn_kernel<<<nblocks, 256>>>(bias, out, N);

    cudaEventDestroy(evFork);
    cudaEventDestroy(evJoin);
    cudaStreamDestroy(s1);
}

// round 5
// speedup vs baseline: 1.9429x; 1.0726x over previous
#include <cuda_runtime.h>
#include <cuda_bf16.h>
#include <math.h>

// N=50000, E=800000, IN=128, H=8, EMB=32, OUT=16, EF=7
#define MAXN 50000
#define MAXE 800000
#define INF_DIM 128
#define NCOLS 256          // wcat cols: Aq(64) | Ak(64) | v(128)
#define PA_STRIDE 192      // projA row: Aq(64) | v(128)

typedef unsigned long long u64t;

__device__ __forceinline__ u64t dup2(float x) {
    u64t r; asm("mov.b64 %0, {%1, %1};" : "=l"(r) : "f"(x)); return r;
}
__device__ __forceinline__ u64t ffma2(u64t a, u64t b, u64t c) {
    u64t d; asm("fma.rn.f32x2 %0, %1, %2, %3;" : "=l"(d) : "l"(a), "l"(b), "l"(c)); return d;
}
__device__ __forceinline__ u64t fmul2(u64t a, u64t b) {
    u64t d; asm("mul.rn.f32x2 %0, %1, %2;" : "=l"(d) : "l"(a), "l"(b)); return d;
}
__device__ __forceinline__ float2 unpack2(u64t a) {
    float2 f; asm("mov.b64 {%0, %1}, %2;" : "=f"(f.x), "=f"(f.y) : "l"(a)); return f;
}

// -------- device scratch --------
__device__ int   g_deg[MAXN];
__device__ int   g_cnt[MAXN];
__device__ int   g_offs[MAXN + 1];
__device__ int   g_bsum[64];
__device__ int   g_bbase[64];
__device__ int2  g_sidx[MAXE];                         // CSR-permuted (src, orig edge id)
__device__ float g_projA[(size_t)MAXN * PA_STRIDE];
__device__ float g_projK[(size_t)MAXN * 64];
__device__ float g_wcat[INF_DIM * NCOLS];
__device__ float g_wefc8[8 * 128];

// ---------------- prep: combined weights ----------------
__global__ void prep_kernel(const float* __restrict__ Wq, const float* __restrict__ Wk,
                            const float* __restrict__ Wv, const float* __restrict__ Wek,
                            const float* __restrict__ bek, const float* __restrict__ Wefc,
                            const float* __restrict__ befc)
{
    int idx = blockIdx.x * blockDim.x + threadIdx.x;
    if (idx < INF_DIM * NCOLS) {
        int i = idx >> 8;
        int c = idx & 255;
        float r;
        if (c < 128) {
            const float* Wx = (c < 64) ? Wq : Wk;
            int cc = c & 63;
            int h = cc >> 3, f = cc & 7;
            const float* ekrow = (f < 7) ? (Wek + f * 256) : bek;
            float acc = 0.f;
            #pragma unroll
            for (int m = 0; m < 32; ++m)
                acc = fmaf(Wx[i * 256 + h * 32 + m], ekrow[h * 32 + m], acc);
            r = acc;
        } else {
            r = Wv[i * 128 + (c - 128)];
        }
        g_wcat[idx] = r;
    }
    if (idx < 8 * 128) {
        int f = idx >> 7, c = idx & 127;
        g_wefc8[idx] = (f < 7) ? Wefc[f * 128 + c] : befc[c];
    }
}

// ---------------- CSR build ----------------
__global__ void deg_kernel(const int* __restrict__ dst, int E)
{
    int e = blockIdx.x * blockDim.x + threadIdx.x;
    if (e < E) atomicAdd(&g_deg[dst[e]], 1);
}

// local scan; also zeroes g_cnt for the scatter pass
__global__ void scan_local_kernel(int n)
{
    __shared__ int wsum[32];
    int t = threadIdx.x, lane = t & 31, wid = t >> 5;
    int i = blockIdx.x * 1024 + t;
    int v = (i < n) ? g_deg[i] : 0;
    if (i < n) g_cnt[i] = 0;
    int x = v;
    #pragma unroll
    for (int d = 1; d < 32; d <<= 1) {
        int y = __shfl_up_sync(0xffffffffu, x, d);
        if (lane >= d) x += y;
    }
    if (lane == 31) wsum[wid] = x;
    __syncthreads();
    if (wid == 0) {
        int y = wsum[lane];
        #pragma unroll
        for (int d = 1; d < 32; d <<= 1) {
            int z = __shfl_up_sync(0xffffffffu, y, d);
            if (lane >= d) y += z;
        }
        wsum[lane] = y;
    }
    __syncthreads();
    int excl = ((wid > 0) ? wsum[wid - 1] : 0) + (x - v);
    if (i < n) g_offs[i] = excl;
    if (t == 1023) g_bsum[blockIdx.x] = wsum[31];
}

__global__ void scan_base_kernel(int nb, int n)
{
    __shared__ int wsum[32];
    int t = threadIdx.x, lane = t & 31, wid = t >> 5;
    int v = (t < nb) ? g_bsum[t] : 0;
    int x = v;
    #pragma unroll
    for (int d = 1; d < 32; d <<= 1) {
        int y = __shfl_up_sync(0xffffffffu, x, d);
        if (lane >= d) x += y;
    }
    if (lane == 31) wsum[wid] = x;
    __syncthreads();
    if (wid == 0) {
        int y = wsum[lane];
        #pragma unroll
        for (int d = 1; d < 32; d <<= 1) {
            int z = __shfl_up_sync(0xffffffffu, y, d);
            if (lane >= d) y += z;
        }
        wsum[lane] = y;
    }
    __syncthreads();
    int excl = ((wid > 0) ? wsum[wid - 1] : 0) + (x - v);
    if (t < nb) g_bbase[t] = excl;
    if (t == 0) g_offs[n] = g_bsum[n >> 10];   // end(last node) = bsum + bbase = E
}

__global__ void scatter_kernel(const int* __restrict__ src, const int* __restrict__ dst, int E)
{
    int e = blockIdx.x * blockDim.x + threadIdx.x;
    if (e >= E) return;
    int d = dst[e];
    int p = g_offs[d] + g_bbase[d >> 10] + atomicAdd(&g_cnt[d], 1);
    g_sidx[p] = make_int2(src[e], e);
}

// ---------------- node projection GEMM (128x128x16, 8x8 microtile, FFMA2) ----------------
#define GBM 128
#define GBN 128
#define GBK 16
__global__ void __launch_bounds__(256) sgemm_kernel(const float* __restrict__ A, int M)
{
    __shared__ float As[GBK][GBM];
    __shared__ float Bs[GBK][GBN];
    int tid = threadIdx.x;
    int brow = blockIdx.y * GBM;
    int bcol = blockIdx.x * GBN;      // 0 or 128
    int ty = tid >> 4, tx = tid & 15; // 16x16 threads, 8x8 microtile
    u64t acc2[4][8];                  // m-pairs (rows 2m2,2m2+1) x 8 cols
    #pragma unroll
    for (int m = 0; m < 4; ++m)
        #pragma unroll
        for (int j = 0; j < 8; ++j) acc2[m][j] = 0ull;

    for (int k0 = 0; k0 < INF_DIM; k0 += GBK) {
        #pragma unroll
        for (int i = 0; i < 2; ++i) {
            int q = tid * 2 + i;          // 0..511
            int r = q >> 2;               // 0..127
            int kq = (q & 3) * 4;         // 0,4,8,12
            int gr = brow + r;
            float4 a4 = (gr < M) ? *(const float4*)(&A[(size_t)gr * INF_DIM + k0 + kq])
                                 : make_float4(0.f, 0.f, 0.f, 0.f);
            As[kq + 0][r] = a4.x; As[kq + 1][r] = a4.y;
            As[kq + 2][r] = a4.z; As[kq + 3][r] = a4.w;
        }
        #pragma unroll
        for (int i = 0; i < 2; ++i) {
            int q = tid + i * 256;        // 0..511
            int kk = q >> 5;              // 0..15
            int c = (q & 31) * 4;
            *(float4*)(&Bs[kk][c]) = *(const float4*)(&g_wcat[(k0 + kk) * NCOLS + bcol + c]);
        }
        __syncthreads();
        #pragma unroll
        for (int kk = 0; kk < GBK; ++kk) {
            // A pairs loaded directly as 64-bit packed (rows adjacent in As)
            u64t ar2[4];
            ulonglong2 au0 = *(ulonglong2*)&As[kk][ty * 8];
            ulonglong2 au1 = *(ulonglong2*)&As[kk][ty * 8 + 4];
            ar2[0] = au0.x; ar2[1] = au0.y; ar2[2] = au1.x; ar2[3] = au1.y;
            float br[8];
            *(float4*)&br[0] = *(float4*)&Bs[kk][tx * 8];
            *(float4*)&br[4] = *(float4*)&Bs[kk][tx * 8 + 4];
            u64t brd[8];
            #pragma unroll
            for (int j = 0; j < 8; ++j) brd[j] = dup2(br[j]);
            #pragma unroll
            for (int m = 0; m < 4; ++m)
                #pragma unroll
                for (int j = 0; j < 8; ++j)
                    acc2[m][j] = ffma2(ar2[m], brd[j], acc2[m][j]);
        }
        __syncthreads();
    }

    // routing: global col block = bcol + tx*8
    int gcol = bcol + tx * 8;
    float* dstp; int cstart; int stride;
    if (gcol < 64)        { dstp = g_projA; cstart = gcol;      stride = PA_STRIDE; }
    else if (gcol < 128)  { dstp = g_projK; cstart = gcol - 64; stride = 64; }
    else                  { dstp = g_projA; cstart = gcol - 64; stride = PA_STRIDE; }

    #pragma unroll
    for (int m = 0; m < 4; ++m) {
        int gr0 = brow + ty * 8 + 2 * m;
        float2 c0 = unpack2(acc2[m][0]), c1 = unpack2(acc2[m][1]);
        float2 c2 = unpack2(acc2[m][2]), c3 = unpack2(acc2[m][3]);
        float2 c4 = unpack2(acc2[m][4]), c5 = unpack2(acc2[m][5]);
        float2 c6 = unpack2(acc2[m][6]), c7 = unpack2(acc2[m][7]);
        if (gr0 < M) {
            *(float4*)(&dstp[(size_t)gr0 * stride + cstart])     = make_float4(c0.x, c1.x, c2.x, c3.x);
            *(float4*)(&dstp[(size_t)gr0 * stride + cstart + 4]) = make_float4(c4.x, c5.x, c6.x, c7.x);
        }
        if (gr0 + 1 < M) {
            *(float4*)(&dstp[(size_t)(gr0 + 1) * stride + cstart])     = make_float4(c0.y, c1.y, c2.y, c3.y);
            *(float4*)(&dstp[(size_t)(gr0 + 1) * stride + cstart + 4]) = make_float4(c4.y, c5.y, c6.y, c7.y);
        }
    }
}

// ---------------- fused edge attention + aggregation (FFMA2) ----------------
// One warp per dst node. Lane l: head h=l>>2, channels ch=4l..4l+3.
__global__ void __launch_bounds__(256) edge_attn_kernel(
    const float* __restrict__ bond, const float* __restrict__ bias,
    float* __restrict__ out, int n)
{
    int warp = blockIdx.x * (blockDim.x >> 5) + (threadIdx.x >> 5);
    if (warp >= n) return;
    int l = threadIdx.x & 31;
    int jj = l & 3;
    int start = g_offs[warp]     + g_bbase[warp >> 10];
    int end   = g_offs[warp + 1] + g_bbase[(warp + 1) >> 10];

    float2 akp = *(const float2*)(&g_projK[(size_t)warp * 64 + 2 * l]);

    int ch = 4 * l;
    u64t wef2[8][2];   // packed channel pairs per bond-feature row (row 7 = bias befc)
    #pragma unroll
    for (int f = 0; f < 8; ++f) {
        ulonglong2 w = *(const ulonglong2*)(&g_wefc8[f * 128 + ch]);
        wef2[f][0] = w.x; wef2[f][1] = w.y;
    }
    float4 b4 = *(const float4*)(&bias[ch]);

    float denom = 0.f;
    u64t a2[2] = {0ull, 0ull};

    int deg = end - start;
    if (deg > 0) {
        // prologue: load edge 0 fully, edge index 1
        int2 se_c = g_sidx[start];
        int2 se_n = (deg > 1) ? g_sidx[start + 1] : se_c;
        const float* bp = bond + (size_t)se_c.y * 7;
        float bc0 = __ldg(bp + 0), bc1 = __ldg(bp + 1), bc2 = __ldg(bp + 2), bc3 = __ldg(bp + 3);
        float bc4 = __ldg(bp + 4), bc5 = __ldg(bp + 5), bc6 = __ldg(bp + 6);
        float2 aq_c = *(const float2*)(&g_projA[(size_t)se_c.x * PA_STRIDE + 2 * l]);
        ulonglong2 v_c = *(const ulonglong2*)(&g_projA[(size_t)se_c.x * PA_STRIDE + 64 + ch]);

        for (int p = 0; p < deg; ++p) {
            // prefetch next edge data
            float bn0 = 0.f, bn1 = 0.f, bn2 = 0.f, bn3 = 0.f, bn4 = 0.f, bn5 = 0.f, bn6 = 0.f;
            float2 aq_n = make_float2(0.f, 0.f);
            ulonglong2 v_n = make_ulonglong2(0ull, 0ull);
            if (p + 1 < deg) {
                const float* bq = bond + (size_t)se_n.y * 7;
                bn0 = __ldg(bq + 0); bn1 = __ldg(bq + 1); bn2 = __ldg(bq + 2); bn3 = __ldg(bq + 3);
                bn4 = __ldg(bq + 4); bn5 = __ldg(bq + 5); bn6 = __ldg(bq + 6);
                aq_n = *(const float2*)(&g_projA[(size_t)se_n.x * PA_STRIDE + 2 * l]);
                v_n  = *(const ulonglong2*)(&g_projA[(size_t)se_n.x * PA_STRIDE + 64 + ch]);
            }
            if (p + 2 < deg) se_n = g_sidx[start + p + 2];

            // logit: lane jj owns bond pair (2jj, 2jj+1); slot 7 is bias (1.0)
            float pb0 = (jj == 0) ? bc0 : (jj == 1) ? bc2 : (jj == 2) ? bc4 : bc6;
            float pb1 = (jj == 0) ? bc1 : (jj == 1) ? bc3 : (jj == 2) ? bc5 : 1.0f;
            float part = pb0 * (aq_c.x + akp.x) + pb1 * (aq_c.y + akp.y);
            part += __shfl_xor_sync(0xffffffffu, part, 1);
            part += __shfl_xor_sync(0xffffffffu, part, 2);
            float w = __expf(part);
            denom += w;

            // ef = bond @ Wefc + befc  (packed pairs)
            u64t d0 = dup2(bc0), d1 = dup2(bc1), d2 = dup2(bc2), d3 = dup2(bc3);
            u64t d4 = dup2(bc4), d5 = dup2(bc5), d6 = dup2(bc6);
            u64t ef0 = wef2[7][0], ef1 = wef2[7][1];
            ef0 = ffma2(d0, wef2[0][0], ef0); ef1 = ffma2(d0, wef2[0][1], ef1);
            ef0 = ffma2(d1, wef2[1][0], ef0); ef1 = ffma2(d1, wef2[1][1], ef1);
            ef0 = ffma2(d2, wef2[2][0], ef0); ef1 = ffma2(d2, wef2[2][1], ef1);
            ef0 = ffma2(d3, wef2[3][0], ef0); ef1 = ffma2(d3, wef2[3][1], ef1);
            ef0 = ffma2(d4, wef2[4][0], ef0); ef1 = ffma2(d4, wef2[4][1], ef1);
            ef0 = ffma2(d5, wef2[5][0], ef0); ef1 = ffma2(d5, wef2[5][1], ef1);
            ef0 = ffma2(d6, wef2[6][0], ef0); ef1 = ffma2(d6, wef2[6][1], ef1);

            // acc += (w * v) * ef
            u64t wd = dup2(w);
            a2[0] = ffma2(fmul2(wd, v_c.x), ef0, a2[0]);
            a2[1] = ffma2(fmul2(wd, v_c.y), ef1, a2[1]);

            // rotate pipeline
            bc0 = bn0; bc1 = bn1; bc2 = bn2; bc3 = bn3; bc4 = bn4; bc5 = bn5; bc6 = bn6;
            aq_c = aq_n; v_c = v_n;
        }
    }

    float4 r;
    if (deg > 0) {
        float inv = 1.0f / denom;
        float2 lo = unpack2(a2[0]), hi = unpack2(a2[1]);
        r.x = fmaf(lo.x, inv, b4.x);
        r.y = fmaf(lo.y, inv, b4.y);
        r.z = fmaf(hi.x, inv, b4.z);
        r.w = fmaf(hi.y, inv, b4.w);
    } else {
        r = b4;
    }
    *(float4*)(&out[(size_t)warp * 128 + ch]) = r;
}

// ---------------- host launcher ----------------
extern "C" void kernel_launch(void* const* d_in, const int* in_sizes, int n_in,
                              void* d_out, int out_size)
{
    const float* feat = (const float*)d_in[0];
    const float* bond = (const float*)d_in[1];
    const int*   src  = (const int*)d_in[2];
    const int*   dst  = (const int*)d_in[3];
    const float* Wq   = (const float*)d_in[4];
    const float* Wk   = (const float*)d_in[5];
    const float* Wv   = (const float*)d_in[6];
    const float* Wek  = (const float*)d_in[7];
    const float* bek  = (const float*)d_in[8];
    const float* Wefc = (const float*)d_in[9];
    const float* befc = (const float*)d_in[10];
    const float* bias = (const float*)d_in[11];
    float* out = (float*)d_out;

    int N = in_sizes[0] / INF_DIM;   // 50000
    int E = in_sizes[2];             // 800000
    int nb = (N + 1023) / 1024;      // 49

    void* deg_ptr = nullptr;
    cudaGetSymbolAddress(&deg_ptr, g_deg);

    cudaStream_t s1;
    cudaStreamCreateWithFlags(&s1, cudaStreamNonBlocking);
    cudaEvent_t evFork, evJoin;
    cudaEventCreateWithFlags(&evFork, cudaEventDisableTiming);
    cudaEventCreateWithFlags(&evJoin, cudaEventDisableTiming);

    cudaEventRecord(evFork, 0);
    cudaStreamWaitEvent(s1, evFork, 0);

    // side stream: weight prep + node projection GEMM
    prep_kernel<<<(INF_DIM * NCOLS + 255) / 256, 256, 0, s1>>>(Wq, Wk, Wv, Wek, bek, Wefc, befc);
    dim3 ggrid(NCOLS / GBN, (N + GBM - 1) / GBM);
    sgemm_kernel<<<ggrid, 256, 0, s1>>>(feat, N);
    cudaEventRecord(evJoin, s1);

    // main stream: CSR build
    cudaMemsetAsync(deg_ptr, 0, (size_t)N * sizeof(int), 0);
    deg_kernel<<<(E + 255) / 256, 256>>>(dst, E);
    scan_local_kernel<<<nb, 1024>>>(N);
    scan_base_kernel<<<1, 1024>>>(nb, N);
    scatter_kernel<<<(E + 255) / 256, 256>>>(src, dst, E);

    cudaStreamWaitEvent(0, evJoin, 0);

    int warps_per_block = 256 / 32;
    int nblocks = (N + warps_per_block - 1) / warps_per_block;
    edge_attn_kernel<<<nblocks, 256>>>(bond, bias, out, N);

    cudaEventDestroy(evFork);
    cudaEventDestroy(evJoin);
    cudaStreamDestroy(s1);
}

// round 6
// speedup vs baseline: 1.9477x; 1.0024x over previous
#include <cuda_runtime.h>
#include <cuda_bf16.h>
#include <math.h>

// N=50000, E=800000, IN=128, H=8, EMB=32, OUT=16, EF=7
#define MAXN 50000
#define MAXE 800000
#define INF_DIM 128
#define NCOLS 256          // wcat cols: Aq(64) | Ak(64) | v(128)
#define PA_STRIDE 192      // projA row: Aq(64) | v(128)

typedef unsigned long long u64t;

__device__ __forceinline__ u64t dup2(float x) {
    u64t r; asm("mov.b64 %0, {%1, %1};" : "=l"(r) : "f"(x)); return r;
}
__device__ __forceinline__ u64t ffma2(u64t a, u64t b, u64t c) {
    u64t d; asm("fma.rn.f32x2 %0, %1, %2, %3;" : "=l"(d) : "l"(a), "l"(b), "l"(c)); return d;
}
__device__ __forceinline__ u64t fmul2(u64t a, u64t b) {
    u64t d; asm("mul.rn.f32x2 %0, %1, %2;" : "=l"(d) : "l"(a), "l"(b)); return d;
}
__device__ __forceinline__ float2 unpack2(u64t a) {
    float2 f; asm("mov.b64 {%0, %1}, %2;" : "=f"(f.x), "=f"(f.y) : "l"(a)); return f;
}

// -------- device scratch --------
__device__ int   g_deg[MAXN];
__device__ int   g_cnt[MAXN];
__device__ int   g_offs[MAXN + 1];
__device__ int   g_bsum[64];
__device__ int   g_bbase[64];
__device__ int2  g_sidx[MAXE];                         // CSR-permuted (src, orig edge id)
__device__ float g_projA[(size_t)MAXN * PA_STRIDE];
__device__ float g_projK[(size_t)MAXN * 64];
__device__ float g_wcat[INF_DIM * NCOLS];
__device__ float g_wefc8[8 * 128];

// ---------------- prep: combined weights ----------------
__global__ void prep_kernel(const float* __restrict__ Wq, const float* __restrict__ Wk,
                            const float* __restrict__ Wv, const float* __restrict__ Wek,
                            const float* __restrict__ bek, const float* __restrict__ Wefc,
                            const float* __restrict__ befc)
{
    int idx = blockIdx.x * blockDim.x + threadIdx.x;
    if (idx < INF_DIM * NCOLS) {
        int i = idx >> 8;
        int c = idx & 255;
        float r;
        if (c < 128) {
            const float* Wx = (c < 64) ? Wq : Wk;
            int cc = c & 63;
            int h = cc >> 3, f = cc & 7;
            const float* ekrow = (f < 7) ? (Wek + f * 256) : bek;
            float acc = 0.f;
            #pragma unroll
            for (int m = 0; m < 32; ++m)
                acc = fmaf(Wx[i * 256 + h * 32 + m], ekrow[h * 32 + m], acc);
            r = acc;
        } else {
            r = Wv[i * 128 + (c - 128)];
        }
        g_wcat[idx] = r;
    }
    if (idx < 8 * 128) {
        int f = idx >> 7, c = idx & 127;
        g_wefc8[idx] = (f < 7) ? Wefc[f * 128 + c] : befc[c];
    }
}

// ---------------- CSR build ----------------
__global__ void deg_kernel(const int* __restrict__ dst, int E)
{
    int e = blockIdx.x * blockDim.x + threadIdx.x;
    if (e < E) atomicAdd(&g_deg[dst[e]], 1);
}

__global__ void scan_local_kernel(int n)
{
    __shared__ int wsum[32];
    int t = threadIdx.x, lane = t & 31, wid = t >> 5;
    int i = blockIdx.x * 1024 + t;
    int v = (i < n) ? g_deg[i] : 0;
    if (i < n) g_cnt[i] = 0;
    int x = v;
    #pragma unroll
    for (int d = 1; d < 32; d <<= 1) {
        int y = __shfl_up_sync(0xffffffffu, x, d);
        if (lane >= d) x += y;
    }
    if (lane == 31) wsum[wid] = x;
    __syncthreads();
    if (wid == 0) {
        int y = wsum[lane];
        #pragma unroll
        for (int d = 1; d < 32; d <<= 1) {
            int z = __shfl_up_sync(0xffffffffu, y, d);
            if (lane >= d) y += z;
        }
        wsum[lane] = y;
    }
    __syncthreads();
    int excl = ((wid > 0) ? wsum[wid - 1] : 0) + (x - v);
    if (i < n) g_offs[i] = excl;
    if (t == 1023) g_bsum[blockIdx.x] = wsum[31];
}

__global__ void scan_base_kernel(int nb, int n)
{
    __shared__ int wsum[32];
    int t = threadIdx.x, lane = t & 31, wid = t >> 5;
    int v = (t < nb) ? g_bsum[t] : 0;
    int x = v;
    #pragma unroll
    for (int d = 1; d < 32; d <<= 1) {
        int y = __shfl_up_sync(0xffffffffu, x, d);
        if (lane >= d) x += y;
    }
    if (lane == 31) wsum[wid] = x;
    __syncthreads();
    if (wid == 0) {
        int y = wsum[lane];
        #pragma unroll
        for (int d = 1; d < 32; d <<= 1) {
            int z = __shfl_up_sync(0xffffffffu, y, d);
            if (lane >= d) y += z;
        }
        wsum[lane] = y;
    }
    __syncthreads();
    int excl = ((wid > 0) ? wsum[wid - 1] : 0) + (x - v);
    if (t < nb) g_bbase[t] = excl;
    if (t == 0) g_offs[n] = g_bsum[n >> 10];   // end(last node) = bsum + bbase = E
}

__global__ void scatter_kernel(const int* __restrict__ src, const int* __restrict__ dst, int E)
{
    int e = blockIdx.x * blockDim.x + threadIdx.x;
    if (e >= E) return;
    int d = dst[e];
    int p = g_offs[d] + g_bbase[d >> 10] + atomicAdd(&g_cnt[d], 1);
    g_sidx[p] = make_int2(src[e], e);
}

// ---------------- node projection GEMM (128x128x16, 8x8 microtile, FFMA2) ----------------
#define GBM 128
#define GBN 128
#define GBK 16
__global__ void __launch_bounds__(256) sgemm_kernel(const float* __restrict__ A, int M)
{
    __shared__ float As[GBK][GBM];
    __shared__ float Bs[GBK][GBN];
    int tid = threadIdx.x;
    int brow = blockIdx.y * GBM;
    int bcol = blockIdx.x * GBN;      // 0 or 128
    int ty = tid >> 4, tx = tid & 15; // 16x16 threads, 8x8 microtile
    u64t acc2[4][8];
    #pragma unroll
    for (int m = 0; m < 4; ++m)
        #pragma unroll
        for (int j = 0; j < 8; ++j) acc2[m][j] = 0ull;

    for (int k0 = 0; k0 < INF_DIM; k0 += GBK) {
        #pragma unroll
        for (int i = 0; i < 2; ++i) {
            int q = tid * 2 + i;
            int r = q >> 2;
            int kq = (q & 3) * 4;
            int gr = brow + r;
            float4 a4 = (gr < M) ? *(const float4*)(&A[(size_t)gr * INF_DIM + k0 + kq])
                                 : make_float4(0.f, 0.f, 0.f, 0.f);
            As[kq + 0][r] = a4.x; As[kq + 1][r] = a4.y;
            As[kq + 2][r] = a4.z; As[kq + 3][r] = a4.w;
        }
        #pragma unroll
        for (int i = 0; i < 2; ++i) {
            int q = tid + i * 256;
            int kk = q >> 5;
            int c = (q & 31) * 4;
            *(float4*)(&Bs[kk][c]) = *(const float4*)(&g_wcat[(k0 + kk) * NCOLS + bcol + c]);
        }
        __syncthreads();
        #pragma unroll
        for (int kk = 0; kk < GBK; ++kk) {
            u64t ar2[4];
            ulonglong2 au0 = *(ulonglong2*)&As[kk][ty * 8];
            ulonglong2 au1 = *(ulonglong2*)&As[kk][ty * 8 + 4];
            ar2[0] = au0.x; ar2[1] = au0.y; ar2[2] = au1.x; ar2[3] = au1.y;
            float br[8];
            *(float4*)&br[0] = *(float4*)&Bs[kk][tx * 8];
            *(float4*)&br[4] = *(float4*)&Bs[kk][tx * 8 + 4];
            u64t brd[8];
            #pragma unroll
            for (int j = 0; j < 8; ++j) brd[j] = dup2(br[j]);
            #pragma unroll
            for (int m = 0; m < 4; ++m)
                #pragma unroll
                for (int j = 0; j < 8; ++j)
                    acc2[m][j] = ffma2(ar2[m], brd[j], acc2[m][j]);
        }
        __syncthreads();
    }

    int gcol = bcol + tx * 8;
    float* dstp; int cstart; int stride;
    if (gcol < 64)        { dstp = g_projA; cstart = gcol;      stride = PA_STRIDE; }
    else if (gcol < 128)  { dstp = g_projK; cstart = gcol - 64; stride = 64; }
    else                  { dstp = g_projA; cstart = gcol - 64; stride = PA_STRIDE; }

    #pragma unroll
    for (int m = 0; m < 4; ++m) {
        int gr0 = brow + ty * 8 + 2 * m;
        float2 c0 = unpack2(acc2[m][0]), c1 = unpack2(acc2[m][1]);
        float2 c2 = unpack2(acc2[m][2]), c3 = unpack2(acc2[m][3]);
        float2 c4 = unpack2(acc2[m][4]), c5 = unpack2(acc2[m][5]);
        float2 c6 = unpack2(acc2[m][6]), c7 = unpack2(acc2[m][7]);
        if (gr0 < M) {
            *(float4*)(&dstp[(size_t)gr0 * stride + cstart])     = make_float4(c0.x, c1.x, c2.x, c3.x);
            *(float4*)(&dstp[(size_t)gr0 * stride + cstart + 4]) = make_float4(c4.x, c5.x, c6.x, c7.x);
        }
        if (gr0 + 1 < M) {
            *(float4*)(&dstp[(size_t)(gr0 + 1) * stride + cstart])     = make_float4(c0.y, c1.y, c2.y, c3.y);
            *(float4*)(&dstp[(size_t)(gr0 + 1) * stride + cstart + 4]) = make_float4(c4.y, c5.y, c6.y, c7.y);
        }
    }
}

// ---------------- fused edge attention + aggregation ----------------
// One warp per dst node. Chunked coalesced sidx load + shfl broadcast;
// depth-1 prefetch of the random gathers (aq, v, bond).
__global__ void __launch_bounds__(256, 3) edge_attn_kernel(
    const float* __restrict__ bond, const float* __restrict__ bias,
    float* __restrict__ out, int n)
{
    int warp = blockIdx.x * (blockDim.x >> 5) + (threadIdx.x >> 5);
    if (warp >= n) return;
    int l = threadIdx.x & 31;
    int jj = l & 3;
    int start = g_offs[warp]     + g_bbase[warp >> 10];
    int end   = g_offs[warp + 1] + g_bbase[(warp + 1) >> 10];

    float2 akp = *(const float2*)(&g_projK[(size_t)warp * 64 + 2 * l]);

    int ch = 4 * l;
    u64t wef2[8][2];
    #pragma unroll
    for (int f = 0; f < 8; ++f) {
        ulonglong2 w = *(const ulonglong2*)(&g_wefc8[f * 128 + ch]);
        wef2[f][0] = w.x; wef2[f][1] = w.y;
    }

    float denom = 0.f;
    u64t a2[2] = {0ull, 0ull};

    for (int cb = start; cb < end; cb += 32) {
        int cnt = min(32, end - cb);
        int2 se = (cb + l < end) ? g_sidx[cb + l] : make_int2(0, 0);

        // prefetch iteration 0
        int s_n = __shfl_sync(0xffffffffu, se.x, 0);
        int e_n = __shfl_sync(0xffffffffu, se.y, 0);
        float2 aq_n = *(const float2*)(&g_projA[(size_t)s_n * PA_STRIDE + 2 * l]);
        ulonglong2 v_n = *(const ulonglong2*)(&g_projA[(size_t)s_n * PA_STRIDE + 64 + ch]);
        const float* bp = bond + (size_t)e_n * 7;
        float bn0 = __ldg(bp + 0), bn1 = __ldg(bp + 1), bn2 = __ldg(bp + 2), bn3 = __ldg(bp + 3);
        float bn4 = __ldg(bp + 4), bn5 = __ldg(bp + 5), bn6 = __ldg(bp + 6);

        for (int p = 0; p < cnt; ++p) {
            float2 aq_c = aq_n;
            ulonglong2 v_c = v_n;
            float bc0 = bn0, bc1 = bn1, bc2 = bn2, bc3 = bn3, bc4 = bn4, bc5 = bn5, bc6 = bn6;

            if (p + 1 < cnt) {
                s_n = __shfl_sync(0xffffffffu, se.x, p + 1);
                e_n = __shfl_sync(0xffffffffu, se.y, p + 1);
                aq_n = *(const float2*)(&g_projA[(size_t)s_n * PA_STRIDE + 2 * l]);
                v_n  = *(const ulonglong2*)(&g_projA[(size_t)s_n * PA_STRIDE + 64 + ch]);
                const float* bq = bond + (size_t)e_n * 7;
                bn0 = __ldg(bq + 0); bn1 = __ldg(bq + 1); bn2 = __ldg(bq + 2); bn3 = __ldg(bq + 3);
                bn4 = __ldg(bq + 4); bn5 = __ldg(bq + 5); bn6 = __ldg(bq + 6);
            }

            // logit: lane jj owns bond pair (2jj, 2jj+1); slot 7 is bias (1.0)
            float pb0 = (jj == 0) ? bc0 : (jj == 1) ? bc2 : (jj == 2) ? bc4 : bc6;
            float pb1 = (jj == 0) ? bc1 : (jj == 1) ? bc3 : (jj == 2) ? bc5 : 1.0f;
            float part = pb0 * (aq_c.x + akp.x) + pb1 * (aq_c.y + akp.y);
            part += __shfl_xor_sync(0xffffffffu, part, 1);
            part += __shfl_xor_sync(0xffffffffu, part, 2);
            float w = __expf(part);
            denom += w;

            // ef = bond @ Wefc + befc (packed channel pairs)
            u64t d0 = dup2(bc0), d1 = dup2(bc1), d2 = dup2(bc2), d3 = dup2(bc3);
            u64t d4 = dup2(bc4), d5 = dup2(bc5), d6 = dup2(bc6);
            u64t ef0 = wef2[7][0], ef1 = wef2[7][1];
            ef0 = ffma2(d0, wef2[0][0], ef0); ef1 = ffma2(d0, wef2[0][1], ef1);
            ef0 = ffma2(d1, wef2[1][0], ef0); ef1 = ffma2(d1, wef2[1][1], ef1);
            ef0 = ffma2(d2, wef2[2][0], ef0); ef1 = ffma2(d2, wef2[2][1], ef1);
            ef0 = ffma2(d3, wef2[3][0], ef0); ef1 = ffma2(d3, wef2[3][1], ef1);
            ef0 = ffma2(d4, wef2[4][0], ef0); ef1 = ffma2(d4, wef2[4][1], ef1);
            ef0 = ffma2(d5, wef2[5][0], ef0); ef1 = ffma2(d5, wef2[5][1], ef1);
            ef0 = ffma2(d6, wef2[6][0], ef0); ef1 = ffma2(d6, wef2[6][1], ef1);

            // acc += (w * v) * ef
            u64t wd = dup2(w);
            a2[0] = ffma2(fmul2(wd, v_c.x), ef0, a2[0]);
            a2[1] = ffma2(fmul2(wd, v_c.y), ef1, a2[1]);
        }
    }

    float4 b4 = *(const float4*)(&bias[ch]);
    float4 r;
    if (end > start) {
        float inv = 1.0f / denom;
        float2 lo = unpack2(a2[0]), hi = unpack2(a2[1]);
        r.x = fmaf(lo.x, inv, b4.x);
        r.y = fmaf(lo.y, inv, b4.y);
        r.z = fmaf(hi.x, inv, b4.z);
        r.w = fmaf(hi.y, inv, b4.w);
    } else {
        r = b4;
    }
    *(float4*)(&out[(size_t)warp * 128 + ch]) = r;
}

// ---------------- host launcher ----------------
extern "C" void kernel_launch(void* const* d_in, const int* in_sizes, int n_in,
                              void* d_out, int out_size)
{
    const float* feat = (const float*)d_in[0];
    const float* bond = (const float*)d_in[1];
    const int*   src  = (const int*)d_in[2];
    const int*   dst  = (const int*)d_in[3];
    const float* Wq   = (const float*)d_in[4];
    const float* Wk   = (const float*)d_in[5];
    const float* Wv   = (const float*)d_in[6];
    const float* Wek  = (const float*)d_in[7];
    const float* bek  = (const float*)d_in[8];
    const float* Wefc = (const float*)d_in[9];
    const float* befc = (const float*)d_in[10];
    const float* bias = (const float*)d_in[11];
    float* out = (float*)d_out;

    int N = in_sizes[0] / INF_DIM;   // 50000
    int E = in_sizes[2];             // 800000
    int nb = (N + 1023) / 1024;      // 49

    void* deg_ptr = nullptr;
    cudaGetSymbolAddress(&deg_ptr, g_deg);

    cudaStream_t s1;
    cudaStreamCreateWithFlags(&s1, cudaStreamNonBlocking);
    cudaEvent_t evFork, evJoin;
    cudaEventCreateWithFlags(&evFork, cudaEventDisableTiming);
    cudaEventCreateWithFlags(&evJoin, cudaEventDisableTiming);

    cudaEventRecord(evFork, 0);
    cudaStreamWaitEvent(s1, evFork, 0);

    prep_kernel<<<(INF_DIM * NCOLS + 255) / 256, 256, 0, s1>>>(Wq, Wk, Wv, Wek, bek, Wefc, befc);
    dim3 ggrid(NCOLS / GBN, (N + GBM - 1) / GBM);
    sgemm_kernel<<<ggrid, 256, 0, s1>>>(feat, N);
    cudaEventRecord(evJoin, s1);

    cudaMemsetAsync(deg_ptr, 0, (size_t)N * sizeof(int), 0);
    deg_kernel<<<(E + 255) / 256, 256>>>(dst, E);
    scan_local_kernel<<<nb, 1024>>>(N);
    scan_base_kernel<<<1, 1024>>>(nb, N);
    scatter_kernel<<<(E + 255) / 256, 256>>>(src, dst, E);

    cudaStreamWaitEvent(0, evJoin, 0);

    int warps_per_block = 256 / 32;
    int nblocks = (N + warps_per_block - 1) / warps_per_block;
    edge_attn_kernel<<<nblocks, 256>>>(bond, bias, out, N);

    cudaEventDestroy(evFork);
    cudaEventDestroy(evJoin);
    cudaStreamDestroy(s1);
}